// round 14
// baseline (speedup 1.0000x reference)
#include <cuda_runtime.h>
#include <math.h>

// ----------------------------- problem constants ----------------------------
#define DDIM 256
#define LSEQ 1024
#define BATCH 2
#define CHK 16
#define NCH 64                     // chunks per sequence
#define NCHUNKS (BATCH * NCH)      // 128 total chunks
#define PPACK (4 * DDIM * DDIM)    // 262144 packed grad elems per chunk
#define EPSR 1.1920929e-07f

// ----------------------------- device scratch -------------------------------
__device__ float g_sn[BATCH * LSEQ * DDIM];     // store-norm rows
__device__ float g_rn[BATCH * LSEQ * DDIM];     // retrieve-norm rows, pre-shifted by C-1
__device__ float g_scal[NCHUNKS * 3];           // lr, mom, decay per chunk
__device__ float g_WT[3 * DDIM * DDIM];         // W1^T, W2^T, W3^T
__device__ float g_S[(size_t)NCHUNKS * PPACK];  // surprise = -lr * grads  (128 MB)
__device__ float g_U[(size_t)NCHUNKS * PPACK];  // cumulative updates      (128 MB)

// ----------------------------- helpers --------------------------------------
__device__ __forceinline__ float sigm(float z) { return 1.f / (1.f + __expf(-z)); }
__device__ __forceinline__ float siluprime(float z) {
    float s = sigm(z);
    return s * (1.f + z * (1.f - s));
}

// y[c][j] (thread j column) += x[16,256](smem) @ W[256,N] column j (ldw stride)
__device__ __forceinline__ void gemm16(const float* __restrict__ xs,
                                       const float* __restrict__ wcol, int ldw,
                                       float acc[CHK]) {
#pragma unroll 2
    for (int k = 0; k < DDIM; k += 4) {
        float w0 = wcol[(k + 0) * ldw];
        float w1 = wcol[(k + 1) * ldw];
        float w2 = wcol[(k + 2) * ldw];
        float w3 = wcol[(k + 3) * ldw];
#pragma unroll
        for (int c = 0; c < CHK; c++) {
            float4 xv = *reinterpret_cast<const float4*>(xs + c * DDIM + k);
            float a = acc[c];
            a = fmaf(xv.x, w0, a);
            a = fmaf(xv.y, w1, a);
            a = fmaf(xv.z, w2, a);
            a = fmaf(xv.w, w3, a);
            acc[c] = a;
        }
    }
}

// same, but weight column is W + U (fast weights)
__device__ __forceinline__ void gemm16_wu(const float* __restrict__ xs,
                                          const float* __restrict__ wcol,
                                          const float* __restrict__ ucol,
                                          float acc[CHK]) {
#pragma unroll 2
    for (int k = 0; k < DDIM; k += 4) {
        float w0 = wcol[(k + 0) * DDIM] + ucol[(k + 0) * DDIM];
        float w1 = wcol[(k + 1) * DDIM] + ucol[(k + 1) * DDIM];
        float w2 = wcol[(k + 2) * DDIM] + ucol[(k + 2) * DDIM];
        float w3 = wcol[(k + 3) * DDIM] + ucol[(k + 3) * DDIM];
#pragma unroll
        for (int c = 0; c < CHK; c++) {
            float4 xv = *reinterpret_cast<const float4*>(xs + c * DDIM + k);
            float a = acc[c];
            a = fmaf(xv.x, w0, a);
            a = fmaf(xv.y, w1, a);
            a = fmaf(xv.z, w2, a);
            a = fmaf(xv.w, w3, a);
            acc[c] = a;
        }
    }
}

// weight grad: Sout[p][j] = nlr * sum_c a[c][p] * d[c][j]   (thread j = column)
__device__ __forceinline__ void gemmB(const float* __restrict__ as,
                                      const float* __restrict__ ds,
                                      float* __restrict__ sout, float nlr, int j) {
    float dj[CHK];
#pragma unroll
    for (int c = 0; c < CHK; c++) dj[c] = ds[c * DDIM + j];
#pragma unroll 2
    for (int p = 0; p < DDIM; p += 4) {
        float a0 = 0.f, a1 = 0.f, a2 = 0.f, a3 = 0.f;
#pragma unroll
        for (int c = 0; c < CHK; c++) {
            float4 av = *reinterpret_cast<const float4*>(as + c * DDIM + p);
            a0 = fmaf(av.x, dj[c], a0);
            a1 = fmaf(av.y, dj[c], a1);
            a2 = fmaf(av.z, dj[c], a2);
            a3 = fmaf(av.w, dj[c], a3);
        }
        sout[(p + 0) * DDIM + j] = nlr * a0;
        sout[(p + 1) * DDIM + j] = nlr * a1;
        sout[(p + 2) * DDIM + j] = nlr * a2;
        sout[(p + 3) * DDIM + j] = nlr * a3;
    }
}

// ------------------ K1: rmsnorms (store + shifted retrieve) -----------------
__global__ __launch_bounds__(256) void k_norms(const float* __restrict__ seq,
                                               const float* __restrict__ w_store,
                                               const float* __restrict__ w_ret) {
    int gt = blockIdx.x;  // global token 0..2047
    int d = threadIdx.x;
    float x = seq[gt * DDIM + d];
    __shared__ float red[256];
    red[d] = x * x;
    __syncthreads();
    for (int s = 128; s > 0; s >>= 1) {
        if (d < s) red[d] += red[d + s];
        __syncthreads();
    }
    float r = rsqrtf(red[0] * (1.f / DDIM) + EPSR);
    g_sn[gt * DDIM + d] = x * r * w_store[d];
    float rv = x * r * w_ret[d];
    int b = gt >> 10, t = gt & (LSEQ - 1);
    // rn_padded[b, t-(C-1)] = rmsnorm(seq)[b, t]; tail rows are zero
    if (t >= CHK - 1)
        g_rn[(b * LSEQ + t - (CHK - 1)) * DDIM + d] = rv;
    else
        g_rn[(b * LSEQ + (LSEQ - (CHK - 1)) + t) * DDIM + d] = 0.f;
}

// ------------------ K2: per-chunk gate scalars -------------------------------
__global__ __launch_bounds__(256) void k_gates(const float* __restrict__ wa,
                                               const float* __restrict__ wm,
                                               const float* __restrict__ wd) {
    int ci = blockIdx.x;
    int d = threadIdx.x;
    const float* base = g_sn + ci * (CHK * DDIM) + d;
    float s = 0.f;
#pragma unroll
    for (int c = 0; c < CHK; c++) s += base[c * DDIM];
    float m = s * (1.f / CHK);
    float v[3] = {m * wa[d], m * wm[d], m * wd[d]};
    __shared__ float red[256];
    for (int i = 0; i < 3; i++) {
        red[d] = v[i];
        __syncthreads();
        for (int s2 = 128; s2 > 0; s2 >>= 1) {
            if (d < s2) red[d] += red[d + s2];
            __syncthreads();
        }
        if (d == 0) g_scal[ci * 3 + i] = 1.f / (1.f + __expf(-red[0]));
        __syncthreads();
    }
}

// ------------------ K3: transpose W1..W3 for backward ------------------------
__global__ __launch_bounds__(256) void k_transpose(const float* __restrict__ W1,
                                                   const float* __restrict__ W2,
                                                   const float* __restrict__ W3) {
    __shared__ float tile[32][33];
    int m = blockIdx.z;
    const float* W = (m == 0) ? W1 : (m == 1) ? W2 : W3;
    int bx = blockIdx.x * 32, by = blockIdx.y * 32;
    int x = threadIdx.x, y = threadIdx.y;  // 32 x 8
    for (int i = 0; i < 32; i += 8) tile[y + i][x] = W[(by + y + i) * DDIM + bx + x];
    __syncthreads();
    for (int i = 0; i < 32; i += 8)
        g_WT[m * DDIM * DDIM + (bx + y + i) * DDIM + by + x] = tile[x][y + i];
}

// ------------------ K4: per-chunk fwd + bwd grads → S ------------------------
__global__ __launch_bounds__(256) void k_grad(const float* __restrict__ Wkv,
                                              const float* __restrict__ W0,
                                              const float* __restrict__ W1,
                                              const float* __restrict__ W2,
                                              const float* __restrict__ W3) {
    extern __shared__ float sm[];
    float* Bk  = sm + 0 * 4096;  // keys (a0)
    float* Bv  = sm + 1 * 4096;  // vals -> dz3 -> dz1
    float* Bz0 = sm + 2 * 4096;
    float* Ba1 = sm + 3 * 4096;
    float* Bz1 = sm + 4 * 4096;
    float* Ba2 = sm + 5 * 4096;
    float* Bz2 = sm + 6 * 4096;
    float* Ba3 = sm + 7 * 4096;
    float* Bd  = sm + 8 * 4096;  // dz2 -> dz0
    float* Bsn = sm + 9 * 4096;

    int ci = blockIdx.x;
    int j = threadIdx.x;

    // load store-normed chunk rows [16,256]
    {
        const float4* src = reinterpret_cast<const float4*>(g_sn + (size_t)ci * CHK * DDIM);
        float4* dst = reinterpret_cast<float4*>(Bsn);
        for (int i = j; i < CHK * DDIM / 4; i += 256) dst[i] = src[i];
    }
    __syncthreads();

    float acc[CHK];
    // keys = sn @ Wkv[:, :D]
#pragma unroll
    for (int c = 0; c < CHK; c++) acc[c] = 0.f;
    gemm16(Bsn, Wkv + j, 2 * DDIM, acc);
#pragma unroll
    for (int c = 0; c < CHK; c++) Bk[c * DDIM + j] = acc[c];
    // vals = sn @ Wkv[:, D:]
#pragma unroll
    for (int c = 0; c < CHK; c++) acc[c] = 0.f;
    gemm16(Bsn, Wkv + DDIM + j, 2 * DDIM, acc);
#pragma unroll
    for (int c = 0; c < CHK; c++) Bv[c * DDIM + j] = acc[c];
    __syncthreads();

    // z0 = keys @ W0 ; a1 = silu(z0)
#pragma unroll
    for (int c = 0; c < CHK; c++) acc[c] = 0.f;
    gemm16(Bk, W0 + j, DDIM, acc);
#pragma unroll
    for (int c = 0; c < CHK; c++) {
        float z = acc[c];
        Bz0[c * DDIM + j] = z;
        Ba1[c * DDIM + j] = z * sigm(z);
    }
    __syncthreads();
    // z1 = a1 @ W1 ; a2 = silu(z1)
#pragma unroll
    for (int c = 0; c < CHK; c++) acc[c] = 0.f;
    gemm16(Ba1, W1 + j, DDIM, acc);
#pragma unroll
    for (int c = 0; c < CHK; c++) {
        float z = acc[c];
        Bz1[c * DDIM + j] = z;
        Ba2[c * DDIM + j] = z * sigm(z);
    }
    __syncthreads();
    // z2 = a2 @ W2 ; a3 = silu(z2)
#pragma unroll
    for (int c = 0; c < CHK; c++) acc[c] = 0.f;
    gemm16(Ba2, W2 + j, DDIM, acc);
#pragma unroll
    for (int c = 0; c < CHK; c++) {
        float z = acc[c];
        Bz2[c * DDIM + j] = z;
        Ba3[c * DDIM + j] = z * sigm(z);
    }
    __syncthreads();
    // pred = a3 @ W3 ; dz3 = 2*(pred - vals)/D  (in place into Bv)
#pragma unroll
    for (int c = 0; c < CHK; c++) acc[c] = 0.f;
    gemm16(Ba3, W3 + j, DDIM, acc);
#pragma unroll
    for (int c = 0; c < CHK; c++)
        Bv[c * DDIM + j] = (acc[c] - Bv[c * DDIM + j]) * (2.f / DDIM);
    __syncthreads();

    float nlr = -g_scal[ci * 3 + 0];
    float* Sc = g_S + (size_t)ci * PPACK;

    // gW3
    gemmB(Ba3, Bv, Sc + 3 * DDIM * DDIM, nlr, j);
    // dz2 = (dz3 @ W3^T) * silu'(z2)  -> Bd
#pragma unroll
    for (int c = 0; c < CHK; c++) acc[c] = 0.f;
    gemm16(Bv, g_WT + 2 * DDIM * DDIM + j, DDIM, acc);
#pragma unroll
    for (int c = 0; c < CHK; c++)
        Bd[c * DDIM + j] = acc[c] * siluprime(Bz2[c * DDIM + j]);
    __syncthreads();
    // gW2
    gemmB(Ba2, Bd, Sc + 2 * DDIM * DDIM, nlr, j);
    // dz1 = (dz2 @ W2^T) * silu'(z1) -> Bv
#pragma unroll
    for (int c = 0; c < CHK; c++) acc[c] = 0.f;
    gemm16(Bd, g_WT + 1 * DDIM * DDIM + j, DDIM, acc);
#pragma unroll
    for (int c = 0; c < CHK; c++)
        Bv[c * DDIM + j] = acc[c] * siluprime(Bz1[c * DDIM + j]);
    __syncthreads();
    // gW1
    gemmB(Ba1, Bv, Sc + 1 * DDIM * DDIM, nlr, j);
    // dz0 = (dz1 @ W1^T) * silu'(z0) -> Bd
#pragma unroll
    for (int c = 0; c < CHK; c++) acc[c] = 0.f;
    gemm16(Bv, g_WT + 0 * DDIM * DDIM + j, DDIM, acc);
#pragma unroll
    for (int c = 0; c < CHK; c++)
        Bd[c * DDIM + j] = acc[c] * siluprime(Bz0[c * DDIM + j]);
    __syncthreads();
    // gW0
    gemmB(Bk, Bd, Sc + 0 * DDIM * DDIM, nlr, j);
}

// ------------------ K5: double gated scan over chunks (per element) ----------
__global__ __launch_bounds__(256) void k_scan() {
    int b = blockIdx.y;
    size_t p = (size_t)blockIdx.x * 256 + threadIdx.x;
    __shared__ float sc[NCH * 2];
    if (threadIdx.x < NCH * 2) {
        int n = threadIdx.x >> 1;
        int w = threadIdx.x & 1;
        sc[threadIdx.x] = w ? (1.f - g_scal[(b * NCH + n) * 3 + 2])   // 1 - decay
                            : g_scal[(b * NCH + n) * 3 + 1];          // momentum gate
    }
    __syncthreads();
    const float* Sp = g_S + (size_t)b * NCH * PPACK + p;
    float* Up = g_U + (size_t)b * NCH * PPACK + p;
    float m = 0.f, u = 0.f;
#pragma unroll 8
    for (int n = 0; n < NCH; n++) {
        float s = Sp[(size_t)n * PPACK];
        m = fmaf(sc[2 * n], m, s);
        u = fmaf(sc[2 * n + 1], u, m);
        Up[(size_t)n * PPACK] = u;
    }
}

// ------------------ K6: retrieval MLP + postnorm + shift ---------------------
__global__ __launch_bounds__(256) void k_retrieve(const float* __restrict__ Wq,
                                                  const float* __restrict__ W0,
                                                  const float* __restrict__ W1,
                                                  const float* __restrict__ W2,
                                                  const float* __restrict__ W3,
                                                  const float* __restrict__ w_post,
                                                  float* __restrict__ out) {
    __shared__ __align__(16) float X[4096];
    __shared__ __align__(16) float Y[4096];
    __shared__ float rr[CHK];
    int ci = blockIdx.x;
    int j = threadIdx.x;
    int b = ci >> 6, n = ci & (NCH - 1);

    {
        const float4* src = reinterpret_cast<const float4*>(g_rn + (size_t)ci * CHK * DDIM);
        float4* dst = reinterpret_cast<float4*>(X);
        for (int i = j; i < CHK * DDIM / 4; i += 256) dst[i] = src[i];
    }
    __syncthreads();

    float acc[CHK];
    // q = rn @ Wq -> Y
#pragma unroll
    for (int c = 0; c < CHK; c++) acc[c] = 0.f;
    gemm16(X, Wq + j, DDIM, acc);
#pragma unroll
    for (int c = 0; c < CHK; c++) Y[c * DDIM + j] = acc[c];
    __syncthreads();

    const float* U = g_U + (size_t)ci * PPACK;
    // layer 0
#pragma unroll
    for (int c = 0; c < CHK; c++) acc[c] = 0.f;
    gemm16_wu(Y, W0 + j, U + 0 * DDIM * DDIM + j, acc);
#pragma unroll
    for (int c = 0; c < CHK; c++) { float z = acc[c]; X[c * DDIM + j] = z * sigm(z); }
    __syncthreads();
    // layer 1
#pragma unroll
    for (int c = 0; c < CHK; c++) acc[c] = 0.f;
    gemm16_wu(X, W1 + j, U + 1 * DDIM * DDIM + j, acc);
#pragma unroll
    for (int c = 0; c < CHK; c++) { float z = acc[c]; Y[c * DDIM + j] = z * sigm(z); }
    __syncthreads();
    // layer 2
#pragma unroll
    for (int c = 0; c < CHK; c++) acc[c] = 0.f;
    gemm16_wu(Y, W2 + j, U + 2 * DDIM * DDIM + j, acc);
#pragma unroll
    for (int c = 0; c < CHK; c++) { float z = acc[c]; X[c * DDIM + j] = z * sigm(z); }
    __syncthreads();
    // layer 3 (raw)
#pragma unroll
    for (int c = 0; c < CHK; c++) acc[c] = 0.f;
    gemm16_wu(X, W3 + j, U + 3 * DDIM * DDIM + j, acc);
#pragma unroll
    for (int c = 0; c < CHK; c++) Y[c * DDIM + j] = acc[c];
    __syncthreads();

    // post rmsnorm per row
    int warp = j >> 5, lane = j & 31;
    for (int c = warp; c < CHK; c += 8) {
        float s = 0.f;
        for (int i = lane; i < DDIM; i += 32) {
            float v = Y[c * DDIM + i];
            s = fmaf(v, v, s);
        }
        for (int o = 16; o; o >>= 1) s += __shfl_xor_sync(0xffffffffu, s, o);
        if (lane == 0) rr[c] = rsqrtf(s * (1.f / DDIM) + EPSR);
    }
    __syncthreads();

    // shift by C-1 and write
#pragma unroll
    for (int c = 0; c < CHK; c++) {
        int tdst = n * CHK + c + (CHK - 1);
        if (tdst < LSEQ)
            out[(b * LSEQ + tdst) * DDIM + j] = Y[c * DDIM + j] * rr[c] * w_post[j];
    }
    if (n == 0) {
#pragma unroll
        for (int c = 0; c < CHK - 1; c++) out[(b * LSEQ + c) * DDIM + j] = 0.f;
    }
}

// ----------------------------- launcher --------------------------------------
extern "C" void kernel_launch(void* const* d_in, const int* in_sizes, int n_in,
                              void* d_out, int out_size) {
    (void)in_sizes; (void)n_in; (void)out_size;
    const float* seq  = (const float*)d_in[0];
    const float* w_sn = (const float*)d_in[1];
    const float* w_rn = (const float*)d_in[2];
    const float* w_pn = (const float*)d_in[3];
    const float* Wq   = (const float*)d_in[4];
    const float* Wkv  = (const float*)d_in[5];
    const float* w_ad = (const float*)d_in[6];
    const float* w_mo = (const float*)d_in[7];
    const float* w_de = (const float*)d_in[8];
    const float* W0   = (const float*)d_in[9];
    const float* W1   = (const float*)d_in[10];
    const float* W2   = (const float*)d_in[11];
    const float* W3   = (const float*)d_in[12];
    float* out = (float*)d_out;

    const int grad_smem = 10 * 4096 * (int)sizeof(float);  // 160 KB
    cudaFuncSetAttribute(k_grad, cudaFuncAttributeMaxDynamicSharedMemorySize, grad_smem);

    k_norms<<<BATCH * LSEQ, 256>>>(seq, w_sn, w_rn);
    k_gates<<<NCHUNKS, 256>>>(w_ad, w_mo, w_de);
    k_transpose<<<dim3(8, 8, 3), dim3(32, 8)>>>(W1, W2, W3);
    k_grad<<<NCHUNKS, 256, grad_smem>>>(Wkv, W0, W1, W2, W3);
    k_scan<<<dim3(PPACK / 256, BATCH), 256>>>();
    k_retrieve<<<NCHUNKS, 256>>>(Wq, W0, W1, W2, W3, w_pn, out);
}

// round 15
// speedup vs baseline: 1.0592x; 1.0592x over previous
#include <cuda_runtime.h>
#include <math.h>

// ----------------------------- problem constants ----------------------------
#define DDIM 256
#define LSEQ 1024
#define BATCH 2
#define CHK 16
#define NCH 64                     // chunks per sequence
#define NCHUNKS (BATCH * NCH)      // 128 total chunks
#define PPACK (4 * DDIM * DDIM)    // 262144 packed grad elems per chunk
#define WSZ (DDIM * DDIM)          // 65536
#define EPSR 1.1920929e-07f

// ----------------------------- device scratch -------------------------------
__device__ float g_sn[BATCH * LSEQ * DDIM];     // store-norm rows
__device__ float g_rn[BATCH * LSEQ * DDIM];     // retrieve-norm rows, pre-shifted by C-1
__device__ float g_scal[NCHUNKS * 3];           // lr, mom, decay per chunk
__device__ float g_WT[3 * WSZ];                 // W1^T, W2^T, W3^T
__device__ float g_S[(size_t)NCHUNKS * PPACK];  // surprise = -lr * grads  (128 MB)
__device__ float g_U[(size_t)NCHUNKS * PPACK];  // cumulative updates      (128 MB)

// ----------------------------- helpers --------------------------------------
__device__ __forceinline__ float sigm(float z) { return 1.f / (1.f + __expf(-z)); }
__device__ __forceinline__ float siluprime(float z) {
    float s = sigm(z);
    return s * (1.f + z * (1.f - s));
}

// acc[c] += x[rows,256](smem, xs pre-offset to this thread's rows) @ W col j
template <int R>
__device__ __forceinline__ void gemmN(const float* __restrict__ xs,
                                      const float* __restrict__ wcol, int ldw,
                                      float acc[R]) {
#pragma unroll 4
    for (int k = 0; k < DDIM; k += 4) {
        float w0 = wcol[(k + 0) * ldw];
        float w1 = wcol[(k + 1) * ldw];
        float w2 = wcol[(k + 2) * ldw];
        float w3 = wcol[(k + 3) * ldw];
#pragma unroll
        for (int c = 0; c < R; c++) {
            float4 xv = *reinterpret_cast<const float4*>(xs + c * DDIM + k);
            float a = acc[c];
            a = fmaf(xv.x, w0, a);
            a = fmaf(xv.y, w1, a);
            a = fmaf(xv.z, w2, a);
            a = fmaf(xv.w, w3, a);
            acc[c] = a;
        }
    }
}

// fast-weight variant: weight column is W + U
template <int R>
__device__ __forceinline__ void gemmWU(const float* __restrict__ xs,
                                       const float* __restrict__ wcol,
                                       const float* __restrict__ ucol,
                                       float acc[R]) {
#pragma unroll 2
    for (int k = 0; k < DDIM; k += 4) {
        float w0 = wcol[(k + 0) * DDIM] + ucol[(k + 0) * DDIM];
        float w1 = wcol[(k + 1) * DDIM] + ucol[(k + 1) * DDIM];
        float w2 = wcol[(k + 2) * DDIM] + ucol[(k + 2) * DDIM];
        float w3 = wcol[(k + 3) * DDIM] + ucol[(k + 3) * DDIM];
#pragma unroll
        for (int c = 0; c < R; c++) {
            float4 xv = *reinterpret_cast<const float4*>(xs + c * DDIM + k);
            float a = acc[c];
            a = fmaf(xv.x, w0, a);
            a = fmaf(xv.y, w1, a);
            a = fmaf(xv.z, w2, a);
            a = fmaf(xv.w, w3, a);
            acc[c] = a;
        }
    }
}

// weight grad (half): Sout[p][j] = nlr * sum_c a[c][p] * d[c][j], p in [p0,p0+128)
__device__ __forceinline__ void gemmBh(const float* __restrict__ as,
                                       const float* __restrict__ ds,
                                       float* __restrict__ sout,
                                       float nlr, int j, int p0) {
    float dj[CHK];
#pragma unroll
    for (int c = 0; c < CHK; c++) dj[c] = ds[c * DDIM + j] * nlr;
#pragma unroll 2
    for (int p = p0; p < p0 + 128; p += 4) {
        float a0 = 0.f, a1 = 0.f, a2 = 0.f, a3 = 0.f;
#pragma unroll
        for (int c = 0; c < CHK; c++) {
            float4 av = *reinterpret_cast<const float4*>(as + c * DDIM + p);
            a0 = fmaf(av.x, dj[c], a0);
            a1 = fmaf(av.y, dj[c], a1);
            a2 = fmaf(av.z, dj[c], a2);
            a3 = fmaf(av.w, dj[c], a3);
        }
        sout[(p + 0) * DDIM + j] = a0;
        sout[(p + 1) * DDIM + j] = a1;
        sout[(p + 2) * DDIM + j] = a2;
        sout[(p + 3) * DDIM + j] = a3;
    }
}

// ------------------ K1: rmsnorms (store + shifted retrieve) -----------------
__global__ __launch_bounds__(256) void k_norms(const float* __restrict__ seq,
                                               const float* __restrict__ w_store,
                                               const float* __restrict__ w_ret) {
    int gt = blockIdx.x;  // global token 0..2047
    int d = threadIdx.x;
    float x = seq[gt * DDIM + d];
    __shared__ float red[256];
    red[d] = x * x;
    __syncthreads();
    for (int s = 128; s > 0; s >>= 1) {
        if (d < s) red[d] += red[d + s];
        __syncthreads();
    }
    float r = rsqrtf(red[0] * (1.f / DDIM) + EPSR);
    g_sn[gt * DDIM + d] = x * r * w_store[d];
    float rv = x * r * w_ret[d];
    int b = gt >> 10, t = gt & (LSEQ - 1);
    // rn_padded[b, t-(C-1)] = rmsnorm(seq)[b, t]; tail rows are zero
    if (t >= CHK - 1)
        g_rn[(b * LSEQ + t - (CHK - 1)) * DDIM + d] = rv;
    else
        g_rn[(b * LSEQ + (LSEQ - (CHK - 1)) + t) * DDIM + d] = 0.f;
}

// ------------------ K2: per-chunk gate scalars -------------------------------
__global__ __launch_bounds__(256) void k_gates(const float* __restrict__ wa,
                                               const float* __restrict__ wm,
                                               const float* __restrict__ wd) {
    int ci = blockIdx.x;
    int d = threadIdx.x;
    const float* base = g_sn + ci * (CHK * DDIM) + d;
    float s = 0.f;
#pragma unroll
    for (int c = 0; c < CHK; c++) s += base[c * DDIM];
    float m = s * (1.f / CHK);
    float v[3] = {m * wa[d], m * wm[d], m * wd[d]};
    __shared__ float red[256];
    for (int i = 0; i < 3; i++) {
        red[d] = v[i];
        __syncthreads();
        for (int s2 = 128; s2 > 0; s2 >>= 1) {
            if (d < s2) red[d] += red[d + s2];
            __syncthreads();
        }
        if (d == 0) g_scal[ci * 3 + i] = 1.f / (1.f + __expf(-red[0]));
        __syncthreads();
    }
}

// ------------------ K3: transpose W1..W3 for backward ------------------------
__global__ __launch_bounds__(256) void k_transpose(const float* __restrict__ W1,
                                                   const float* __restrict__ W2,
                                                   const float* __restrict__ W3) {
    __shared__ float tile[32][33];
    int m = blockIdx.z;
    const float* W = (m == 0) ? W1 : (m == 1) ? W2 : W3;
    int bx = blockIdx.x * 32, by = blockIdx.y * 32;
    int x = threadIdx.x, y = threadIdx.y;  // 32 x 8
    for (int i = 0; i < 32; i += 8) tile[y + i][x] = W[(by + y + i) * DDIM + bx + x];
    __syncthreads();
    for (int i = 0; i < 32; i += 8)
        g_WT[m * WSZ + (bx + y + i) * DDIM + by + x] = tile[x][y + i];
}

// ------------------ K4: per-chunk fwd + bwd grads → S ------------------------
// 512 threads: j = tid&255 (output column), h = tid>>8 (row half: rows h*8..h*8+7)
__global__ __launch_bounds__(512) void k_grad(const float* __restrict__ Wkv,
                                              const float* __restrict__ W0,
                                              const float* __restrict__ W1,
                                              const float* __restrict__ W2,
                                              const float* __restrict__ W3) {
    extern __shared__ float sm[];
    float* BX  = sm + 0 * 4096;  // sn -> dz2 -> dz0
    float* BK  = sm + 1 * 4096;  // keys (a0)
    float* BV  = sm + 2 * 4096;  // vals -> dz3 -> dz1
    float* BA1 = sm + 3 * 4096;
    float* BA2 = sm + 4 * 4096;
    float* BA3 = sm + 5 * 4096;

    int ci = blockIdx.x;
    int tid = threadIdx.x;
    int j = tid & 255;
    int h = tid >> 8;
    int r0 = h * 8;

    // load store-normed chunk rows [16,256]
    {
        const float4* src = reinterpret_cast<const float4*>(g_sn + (size_t)ci * CHK * DDIM);
        float4* dst = reinterpret_cast<float4*>(BX);
        for (int i = tid; i < CHK * DDIM / 4; i += 512) dst[i] = src[i];
    }
    __syncthreads();

    float acc[8];
    float z0r[8], z1r[8], z2r[8];

    // keys = sn @ Wkv[:, :D]
#pragma unroll
    for (int c = 0; c < 8; c++) acc[c] = 0.f;
    gemmN<8>(BX + r0 * DDIM, Wkv + j, 2 * DDIM, acc);
#pragma unroll
    for (int c = 0; c < 8; c++) BK[(r0 + c) * DDIM + j] = acc[c];
    // vals = sn @ Wkv[:, D:]
#pragma unroll
    for (int c = 0; c < 8; c++) acc[c] = 0.f;
    gemmN<8>(BX + r0 * DDIM, Wkv + DDIM + j, 2 * DDIM, acc);
#pragma unroll
    for (int c = 0; c < 8; c++) BV[(r0 + c) * DDIM + j] = acc[c];
    __syncthreads();

    // z0 = keys @ W0 (regs); a1 = silu(z0)
#pragma unroll
    for (int c = 0; c < 8; c++) acc[c] = 0.f;
    gemmN<8>(BK + r0 * DDIM, W0 + j, DDIM, acc);
#pragma unroll
    for (int c = 0; c < 8; c++) {
        z0r[c] = acc[c];
        BA1[(r0 + c) * DDIM + j] = acc[c] * sigm(acc[c]);
    }
    __syncthreads();
    // z1, a2
#pragma unroll
    for (int c = 0; c < 8; c++) acc[c] = 0.f;
    gemmN<8>(BA1 + r0 * DDIM, W1 + j, DDIM, acc);
#pragma unroll
    for (int c = 0; c < 8; c++) {
        z1r[c] = acc[c];
        BA2[(r0 + c) * DDIM + j] = acc[c] * sigm(acc[c]);
    }
    __syncthreads();
    // z2, a3
#pragma unroll
    for (int c = 0; c < 8; c++) acc[c] = 0.f;
    gemmN<8>(BA2 + r0 * DDIM, W2 + j, DDIM, acc);
#pragma unroll
    for (int c = 0; c < 8; c++) {
        z2r[c] = acc[c];
        BA3[(r0 + c) * DDIM + j] = acc[c] * sigm(acc[c]);
    }
    __syncthreads();
    // pred = a3 @ W3 ; dz3 = 2*(pred - vals)/D  (in place into BV)
#pragma unroll
    for (int c = 0; c < 8; c++) acc[c] = 0.f;
    gemmN<8>(BA3 + r0 * DDIM, W3 + j, DDIM, acc);
#pragma unroll
    for (int c = 0; c < 8; c++)
        BV[(r0 + c) * DDIM + j] = (acc[c] - BV[(r0 + c) * DDIM + j]) * (2.f / DDIM);
    __syncthreads();

    float nlr = -g_scal[ci * 3 + 0];
    float* Sc = g_S + (size_t)ci * PPACK;
    int p0 = h * 128;

    // gW3
    gemmBh(BA3, BV, Sc + 3 * WSZ, nlr, j, p0);
    // dz2 = (dz3 @ W3^T) * silu'(z2)  -> BX
#pragma unroll
    for (int c = 0; c < 8; c++) acc[c] = 0.f;
    gemmN<8>(BV + r0 * DDIM, g_WT + 2 * WSZ + j, DDIM, acc);
#pragma unroll
    for (int c = 0; c < 8; c++)
        BX[(r0 + c) * DDIM + j] = acc[c] * siluprime(z2r[c]);
    __syncthreads();
    // gW2
    gemmBh(BA2, BX, Sc + 2 * WSZ, nlr, j, p0);
    // dz1 = (dz2 @ W2^T) * silu'(z1) -> BV
#pragma unroll
    for (int c = 0; c < 8; c++) acc[c] = 0.f;
    gemmN<8>(BX + r0 * DDIM, g_WT + 1 * WSZ + j, DDIM, acc);
#pragma unroll
    for (int c = 0; c < 8; c++)
        BV[(r0 + c) * DDIM + j] = acc[c] * siluprime(z1r[c]);
    __syncthreads();
    // gW1
    gemmBh(BA1, BV, Sc + 1 * WSZ, nlr, j, p0);
    // dz0 = (dz1 @ W1^T) * silu'(z0) -> BX
#pragma unroll
    for (int c = 0; c < 8; c++) acc[c] = 0.f;
    gemmN<8>(BV + r0 * DDIM, g_WT + 0 * WSZ + j, DDIM, acc);
#pragma unroll
    for (int c = 0; c < 8; c++)
        BX[(r0 + c) * DDIM + j] = acc[c] * siluprime(z0r[c]);
    __syncthreads();
    // gW0
    gemmBh(BK, BX, Sc + 0 * WSZ, nlr, j, p0);
}

// ------------------ K5: double gated scan over chunks (float4) ---------------
__global__ __launch_bounds__(256) void k_scan() {
    int b = blockIdx.y;
    __shared__ float sc[NCH * 2];
    if (threadIdx.x < NCH * 2) {
        int n = threadIdx.x >> 1;
        int w = threadIdx.x & 1;
        sc[threadIdx.x] = w ? (1.f - g_scal[(b * NCH + n) * 3 + 2])   // 1 - decay
                            : g_scal[(b * NCH + n) * 3 + 1];          // momentum gate
    }
    __syncthreads();
    size_t p4 = (size_t)blockIdx.x * 256 + threadIdx.x;
    const size_t stride4 = PPACK / 4;
    const float4* Sp = reinterpret_cast<const float4*>(g_S) + (size_t)b * NCH * stride4 + p4;
    float4* Up = reinterpret_cast<float4*>(g_U) + (size_t)b * NCH * stride4 + p4;
    float4 m = {0.f, 0.f, 0.f, 0.f};
    float4 u = {0.f, 0.f, 0.f, 0.f};
#pragma unroll 4
    for (int n = 0; n < NCH; n++) {
        float4 s = Sp[(size_t)n * stride4];
        float gm = sc[2 * n], gd = sc[2 * n + 1];
        m.x = fmaf(gm, m.x, s.x);
        m.y = fmaf(gm, m.y, s.y);
        m.z = fmaf(gm, m.z, s.z);
        m.w = fmaf(gm, m.w, s.w);
        u.x = fmaf(gd, u.x, m.x);
        u.y = fmaf(gd, u.y, m.y);
        u.z = fmaf(gd, u.z, m.z);
        u.w = fmaf(gd, u.w, m.w);
        Up[(size_t)n * stride4] = u;
    }
}

// ------------------ K6: retrieval MLP + postnorm + shift ---------------------
// 1024 threads: j = tid&255 (column), h = tid>>8 (quarter: rows h*4..h*4+3)
__global__ __launch_bounds__(1024) void k_retrieve(const float* __restrict__ Wq,
                                                   const float* __restrict__ W0,
                                                   const float* __restrict__ W1,
                                                   const float* __restrict__ W2,
                                                   const float* __restrict__ W3,
                                                   const float* __restrict__ w_post,
                                                   float* __restrict__ out) {
    __shared__ __align__(16) float X[4096];
    __shared__ __align__(16) float Y[4096];
    __shared__ float rr[CHK];
    int ci = blockIdx.x;
    int tid = threadIdx.x;
    int j = tid & 255;
    int h = tid >> 8;       // 0..3
    int r0 = h * 4;
    int b = ci >> 6, n = ci & (NCH - 1);

    {
        const float4* src = reinterpret_cast<const float4*>(g_rn + (size_t)ci * CHK * DDIM);
        float4* dst = reinterpret_cast<float4*>(X);
        for (int i = tid; i < CHK * DDIM / 4; i += 1024) dst[i] = src[i];
    }
    __syncthreads();

    float acc[4];
    // q = rn @ Wq -> Y
#pragma unroll
    for (int c = 0; c < 4; c++) acc[c] = 0.f;
    gemmN<4>(X + r0 * DDIM, Wq + j, DDIM, acc);
#pragma unroll
    for (int c = 0; c < 4; c++) Y[(r0 + c) * DDIM + j] = acc[c];
    __syncthreads();

    const float* U = g_U + (size_t)ci * PPACK;
    // layer 0
#pragma unroll
    for (int c = 0; c < 4; c++) acc[c] = 0.f;
    gemmWU<4>(Y + r0 * DDIM, W0 + j, U + 0 * WSZ + j, acc);
#pragma unroll
    for (int c = 0; c < 4; c++) { float z = acc[c]; X[(r0 + c) * DDIM + j] = z * sigm(z); }
    __syncthreads();
    // layer 1
#pragma unroll
    for (int c = 0; c < 4; c++) acc[c] = 0.f;
    gemmWU<4>(X + r0 * DDIM, W1 + j, U + 1 * WSZ + j, acc);
#pragma unroll
    for (int c = 0; c < 4; c++) { float z = acc[c]; Y[(r0 + c) * DDIM + j] = z * sigm(z); }
    __syncthreads();
    // layer 2
#pragma unroll
    for (int c = 0; c < 4; c++) acc[c] = 0.f;
    gemmWU<4>(Y + r0 * DDIM, W2 + j, U + 2 * WSZ + j, acc);
#pragma unroll
    for (int c = 0; c < 4; c++) { float z = acc[c]; X[(r0 + c) * DDIM + j] = z * sigm(z); }
    __syncthreads();
    // layer 3 (raw)
#pragma unroll
    for (int c = 0; c < 4; c++) acc[c] = 0.f;
    gemmWU<4>(X + r0 * DDIM, W3 + j, U + 3 * WSZ + j, acc);
#pragma unroll
    for (int c = 0; c < 4; c++) Y[(r0 + c) * DDIM + j] = acc[c];
    __syncthreads();

    // post rmsnorm per row (warps 0..15 each own one row)
    int warp = tid >> 5, lane = tid & 31;
    if (warp < CHK) {
        int c = warp;
        float s = 0.f;
        for (int i = lane; i < DDIM; i += 32) {
            float v = Y[c * DDIM + i];
            s = fmaf(v, v, s);
        }
        for (int o = 16; o; o >>= 1) s += __shfl_xor_sync(0xffffffffu, s, o);
        if (lane == 0) rr[c] = rsqrtf(s * (1.f / DDIM) + EPSR);
    }
    __syncthreads();

    // shift by C-1 and write
    float wp = w_post[j];
#pragma unroll
    for (int cc = 0; cc < 4; cc++) {
        int c = r0 + cc;
        int tdst = n * CHK + c + (CHK - 1);
        if (tdst < LSEQ)
            out[(b * LSEQ + tdst) * DDIM + j] = Y[c * DDIM + j] * rr[c] * wp;
    }
    if (n == 0 && h == 0) {
#pragma unroll
        for (int c = 0; c < CHK - 1; c++) out[(b * LSEQ + c) * DDIM + j] = 0.f;
    }
}

// ----------------------------- launcher --------------------------------------
extern "C" void kernel_launch(void* const* d_in, const int* in_sizes, int n_in,
                              void* d_out, int out_size) {
    (void)in_sizes; (void)n_in; (void)out_size;
    const float* seq  = (const float*)d_in[0];
    const float* w_sn = (const float*)d_in[1];
    const float* w_rn = (const float*)d_in[2];
    const float* w_pn = (const float*)d_in[3];
    const float* Wq   = (const float*)d_in[4];
    const float* Wkv  = (const float*)d_in[5];
    const float* w_ad = (const float*)d_in[6];
    const float* w_mo = (const float*)d_in[7];
    const float* w_de = (const float*)d_in[8];
    const float* W0   = (const float*)d_in[9];
    const float* W1   = (const float*)d_in[10];
    const float* W2   = (const float*)d_in[11];
    const float* W3   = (const float*)d_in[12];
    float* out = (float*)d_out;

    const int grad_smem = 6 * 4096 * (int)sizeof(float);  // 96 KB
    cudaFuncSetAttribute(k_grad, cudaFuncAttributeMaxDynamicSharedMemorySize, grad_smem);

    k_norms<<<BATCH * LSEQ, 256>>>(seq, w_sn, w_rn);
    k_gates<<<NCHUNKS, 256>>>(w_ad, w_mo, w_de);
    k_transpose<<<dim3(8, 8, 3), dim3(32, 8)>>>(W1, W2, W3);
    k_grad<<<NCHUNKS, 512, grad_smem>>>(Wkv, W0, W1, W2, W3);
    k_scan<<<dim3(PPACK / 1024, BATCH), 256>>>();
    k_retrieve<<<NCHUNKS, 1024>>>(Wq, W0, W1, W2, W3, w_pn, out);
}

// round 16
// speedup vs baseline: 1.5045x; 1.4203x over previous
#include <cuda_runtime.h>
#include <math.h>

// ----------------------------- problem constants ----------------------------
#define DDIM 256
#define LSEQ 1024
#define BATCH 2
#define CHK 16
#define NCH 64                     // chunks per sequence
#define NCHUNKS (BATCH * NCH)      // 128 total chunks
#define PPACK (4 * DDIM * DDIM)    // 262144 packed grad elems per chunk
#define WSZ (DDIM * DDIM)          // 65536
#define EPSR 1.1920929e-07f

// ----------------------------- device scratch -------------------------------
__device__ float g_sn[BATCH * LSEQ * DDIM];     // store-norm rows
__device__ float g_rn[BATCH * LSEQ * DDIM];     // retrieve-norm rows, pre-shifted by C-1
__device__ float g_scal[NCHUNKS * 3];           // lr, mom, decay per chunk
__device__ float g_WT[3 * WSZ];                 // W1^T, W2^T, W3^T
__device__ float g_S[(size_t)NCHUNKS * PPACK];  // surprise = -lr * grads  (128 MB)
__device__ float g_U[(size_t)NCHUNKS * PPACK];  // cumulative updates      (128 MB)

// ----------------------------- helpers --------------------------------------
__device__ __forceinline__ float sigm(float z) { return 1.f / (1.f + __expf(-z)); }
__device__ __forceinline__ float siluprime(float z) {
    float s = sigm(z);
    return s * (1.f + z * (1.f - s));
}
__device__ __forceinline__ float4 f4zero() { return make_float4(0.f, 0.f, 0.f, 0.f); }

// Forward-type GEMM fragment: thread accumulates an [8 rows x 4 cols] tile over
// 128 k (its k-half).  xs: smem [.. ,256] pre-offset to this thread's 8 rows.
// wg: global weight pre-offset to this thread's 4 columns. acc[c] = float4 cols.
__device__ __forceinline__ void gf(const float* __restrict__ xs,
                                   const float* __restrict__ wg, int ldw,
                                   int kh, float4 acc[8]) {
    const float* wp = wg + (size_t)(kh * 128) * ldw;
    const float* xp = xs + kh * 128;
#pragma unroll 2
    for (int kk = 0; kk < 128; kk += 4) {
        float4 w0 = *reinterpret_cast<const float4*>(wp);
        float4 w1 = *reinterpret_cast<const float4*>(wp + ldw);
        float4 w2 = *reinterpret_cast<const float4*>(wp + 2 * ldw);
        float4 w3 = *reinterpret_cast<const float4*>(wp + 3 * ldw);
        wp += 4 * ldw;
#pragma unroll
        for (int c = 0; c < 8; c++) {
            float4 xv = *reinterpret_cast<const float4*>(xp + c * DDIM + kk);
            acc[c].x = fmaf(xv.x, w0.x, acc[c].x);
            acc[c].x = fmaf(xv.y, w1.x, acc[c].x);
            acc[c].x = fmaf(xv.z, w2.x, acc[c].x);
            acc[c].x = fmaf(xv.w, w3.x, acc[c].x);
            acc[c].y = fmaf(xv.x, w0.y, acc[c].y);
            acc[c].y = fmaf(xv.y, w1.y, acc[c].y);
            acc[c].y = fmaf(xv.z, w2.y, acc[c].y);
            acc[c].y = fmaf(xv.w, w3.y, acc[c].y);
            acc[c].z = fmaf(xv.x, w0.z, acc[c].z);
            acc[c].z = fmaf(xv.y, w1.z, acc[c].z);
            acc[c].z = fmaf(xv.z, w2.z, acc[c].z);
            acc[c].z = fmaf(xv.w, w3.z, acc[c].z);
            acc[c].w = fmaf(xv.x, w0.w, acc[c].w);
            acc[c].w = fmaf(xv.y, w1.w, acc[c].w);
            acc[c].w = fmaf(xv.z, w2.w, acc[c].w);
            acc[c].w = fmaf(xv.w, w3.w, acc[c].w);
        }
    }
}

// Same but weight = W + U (fast weights), both global, same layout.
__device__ __forceinline__ void gfwu(const float* __restrict__ xs,
                                     const float* __restrict__ wg,
                                     const float* __restrict__ ug,
                                     int kh, float4 acc[8]) {
    const float* wp = wg + (size_t)(kh * 128) * DDIM;
    const float* up = ug + (size_t)(kh * 128) * DDIM;
    const float* xp = xs + kh * 128;
#pragma unroll 2
    for (int kk = 0; kk < 128; kk += 4) {
        float4 w0 = *reinterpret_cast<const float4*>(wp);
        float4 w1 = *reinterpret_cast<const float4*>(wp + DDIM);
        float4 w2 = *reinterpret_cast<const float4*>(wp + 2 * DDIM);
        float4 w3 = *reinterpret_cast<const float4*>(wp + 3 * DDIM);
        float4 u0 = *reinterpret_cast<const float4*>(up);
        float4 u1 = *reinterpret_cast<const float4*>(up + DDIM);
        float4 u2 = *reinterpret_cast<const float4*>(up + 2 * DDIM);
        float4 u3 = *reinterpret_cast<const float4*>(up + 3 * DDIM);
        wp += 4 * DDIM;
        up += 4 * DDIM;
        w0.x += u0.x; w0.y += u0.y; w0.z += u0.z; w0.w += u0.w;
        w1.x += u1.x; w1.y += u1.y; w1.z += u1.z; w1.w += u1.w;
        w2.x += u2.x; w2.y += u2.y; w2.z += u2.z; w2.w += u2.w;
        w3.x += u3.x; w3.y += u3.y; w3.z += u3.z; w3.w += u3.w;
#pragma unroll
        for (int c = 0; c < 8; c++) {
            float4 xv = *reinterpret_cast<const float4*>(xp + c * DDIM + kk);
            acc[c].x = fmaf(xv.x, w0.x, acc[c].x);
            acc[c].x = fmaf(xv.y, w1.x, acc[c].x);
            acc[c].x = fmaf(xv.z, w2.x, acc[c].x);
            acc[c].x = fmaf(xv.w, w3.x, acc[c].x);
            acc[c].y = fmaf(xv.x, w0.y, acc[c].y);
            acc[c].y = fmaf(xv.y, w1.y, acc[c].y);
            acc[c].y = fmaf(xv.z, w2.y, acc[c].y);
            acc[c].y = fmaf(xv.w, w3.y, acc[c].y);
            acc[c].z = fmaf(xv.x, w0.z, acc[c].z);
            acc[c].z = fmaf(xv.y, w1.z, acc[c].z);
            acc[c].z = fmaf(xv.z, w2.z, acc[c].z);
            acc[c].z = fmaf(xv.w, w3.z, acc[c].z);
            acc[c].w = fmaf(xv.x, w0.w, acc[c].w);
            acc[c].w = fmaf(xv.y, w1.w, acc[c].w);
            acc[c].w = fmaf(xv.z, w2.w, acc[c].w);
            acc[c].w = fmaf(xv.w, w3.w, acc[c].w);
        }
    }
}

// k-split reduction: kh==1 half deposits partials; kh==0 half adds them.
// Bred viewed as float4[8][128]; slot = rh*64+g (conflict-free).
__device__ __forceinline__ void kreduce(float4 acc[8], float4* Bred, int kh, int slot) {
    if (kh) {
#pragma unroll
        for (int c = 0; c < 8; c++) Bred[c * 128 + slot] = acc[c];
    }
    __syncthreads();
    if (!kh) {
#pragma unroll
        for (int c = 0; c < 8; c++) {
            float4 t = Bred[c * 128 + slot];
            acc[c].x += t.x; acc[c].y += t.y; acc[c].z += t.z; acc[c].w += t.w;
        }
    }
}

// Weight-grad: Sout[p][q] = nlr * sum_c A[c][p] * D[c][q].
// Thread = (q-group of 4, p-quarter of 64).  d-row (scaled) lives in registers.
__device__ __forceinline__ void gb(const float* __restrict__ A,
                                   const float* __restrict__ D,
                                   float* __restrict__ Sout, float nlr, int tid) {
    int g = tid & 63, pq = tid >> 6;
    int q0 = 4 * g;
    float4 dj[CHK];
#pragma unroll
    for (int c = 0; c < CHK; c++) {
        float4 d = *reinterpret_cast<const float4*>(D + c * DDIM + q0);
        dj[c].x = d.x * nlr; dj[c].y = d.y * nlr;
        dj[c].z = d.z * nlr; dj[c].w = d.w * nlr;
    }
    int pend = pq * 64 + 64;
    for (int p0 = pq * 64; p0 < pend; p0 += 4) {
        float4 r0 = f4zero(), r1 = f4zero(), r2 = f4zero(), r3 = f4zero();
#pragma unroll
        for (int c = 0; c < CHK; c++) {
            float4 a = *reinterpret_cast<const float4*>(A + c * DDIM + p0);  // broadcast
            r0.x = fmaf(a.x, dj[c].x, r0.x); r0.y = fmaf(a.x, dj[c].y, r0.y);
            r0.z = fmaf(a.x, dj[c].z, r0.z); r0.w = fmaf(a.x, dj[c].w, r0.w);
            r1.x = fmaf(a.y, dj[c].x, r1.x); r1.y = fmaf(a.y, dj[c].y, r1.y);
            r1.z = fmaf(a.y, dj[c].z, r1.z); r1.w = fmaf(a.y, dj[c].w, r1.w);
            r2.x = fmaf(a.z, dj[c].x, r2.x); r2.y = fmaf(a.z, dj[c].y, r2.y);
            r2.z = fmaf(a.z, dj[c].z, r2.z); r2.w = fmaf(a.z, dj[c].w, r2.w);
            r3.x = fmaf(a.w, dj[c].x, r3.x); r3.y = fmaf(a.w, dj[c].y, r3.y);
            r3.z = fmaf(a.w, dj[c].z, r3.z); r3.w = fmaf(a.w, dj[c].w, r3.w);
        }
        *reinterpret_cast<float4*>(Sout + (size_t)(p0 + 0) * DDIM + q0) = r0;
        *reinterpret_cast<float4*>(Sout + (size_t)(p0 + 1) * DDIM + q0) = r1;
        *reinterpret_cast<float4*>(Sout + (size_t)(p0 + 2) * DDIM + q0) = r2;
        *reinterpret_cast<float4*>(Sout + (size_t)(p0 + 3) * DDIM + q0) = r3;
    }
}

// ------------------ K1: rmsnorms (store + shifted retrieve) -----------------
__global__ __launch_bounds__(256) void k_norms(const float* __restrict__ seq,
                                               const float* __restrict__ w_store,
                                               const float* __restrict__ w_ret) {
    int gt = blockIdx.x;  // global token 0..2047
    int d = threadIdx.x;
    float x = seq[gt * DDIM + d];
    __shared__ float red[256];
    red[d] = x * x;
    __syncthreads();
    for (int s = 128; s > 0; s >>= 1) {
        if (d < s) red[d] += red[d + s];
        __syncthreads();
    }
    float r = rsqrtf(red[0] * (1.f / DDIM) + EPSR);
    g_sn[gt * DDIM + d] = x * r * w_store[d];
    float rv = x * r * w_ret[d];
    int b = gt >> 10, t = gt & (LSEQ - 1);
    if (t >= CHK - 1)
        g_rn[(b * LSEQ + t - (CHK - 1)) * DDIM + d] = rv;
    else
        g_rn[(b * LSEQ + (LSEQ - (CHK - 1)) + t) * DDIM + d] = 0.f;
}

// ------------------ K2: per-chunk gate scalars -------------------------------
__global__ __launch_bounds__(256) void k_gates(const float* __restrict__ wa,
                                               const float* __restrict__ wm,
                                               const float* __restrict__ wd) {
    int ci = blockIdx.x;
    int d = threadIdx.x;
    const float* base = g_sn + ci * (CHK * DDIM) + d;
    float s = 0.f;
#pragma unroll
    for (int c = 0; c < CHK; c++) s += base[c * DDIM];
    float m = s * (1.f / CHK);
    float v[3] = {m * wa[d], m * wm[d], m * wd[d]};
    __shared__ float red[256];
    for (int i = 0; i < 3; i++) {
        red[d] = v[i];
        __syncthreads();
        for (int s2 = 128; s2 > 0; s2 >>= 1) {
            if (d < s2) red[d] += red[d + s2];
            __syncthreads();
        }
        if (d == 0) g_scal[ci * 3 + i] = 1.f / (1.f + __expf(-red[0]));
        __syncthreads();
    }
}

// ------------------ K3: transpose W1..W3 for backward ------------------------
__global__ __launch_bounds__(256) void k_transpose(const float* __restrict__ W1,
                                                   const float* __restrict__ W2,
                                                   const float* __restrict__ W3) {
    __shared__ float tile[32][33];
    int m = blockIdx.z;
    const float* W = (m == 0) ? W1 : (m == 1) ? W2 : W3;
    int bx = blockIdx.x * 32, by = blockIdx.y * 32;
    int x = threadIdx.x, y = threadIdx.y;  // 32 x 8
    for (int i = 0; i < 32; i += 8) tile[y + i][x] = W[(by + y + i) * DDIM + bx + x];
    __syncthreads();
    for (int i = 0; i < 32; i += 8)
        g_WT[m * WSZ + (bx + y + i) * DDIM + by + x] = tile[x][y + i];
}

// ------------------ K4: per-chunk fwd + bwd grads → S ------------------------
// 256 threads: g = tid&63 (cols 4g..4g+3), rh = (tid>>6)&1 (rows rh*8..),
// kh = tid>>7 (k half).  Warps are uniform in (rh,kh) -> broadcast x loads.
__global__ __launch_bounds__(256) void k_grad(const float* __restrict__ Wkv,
                                              const float* __restrict__ W0,
                                              const float* __restrict__ W1,
                                              const float* __restrict__ W2,
                                              const float* __restrict__ W3) {
    extern __shared__ float sm[];
    float* BX  = sm + 0 * 4096;  // sn -> dz2 -> dz0
    float* BK  = sm + 1 * 4096;  // keys (a0)
    float* BV  = sm + 2 * 4096;  // vals -> dz3 -> dz1
    float* BA1 = sm + 3 * 4096;
    float* BA2 = sm + 4 * 4096;
    float* BA3 = sm + 5 * 4096;
    float* Bz0 = sm + 6 * 4096;
    float* Bz1 = sm + 7 * 4096;
    float* Bz2 = sm + 8 * 4096;
    float4* Bred = reinterpret_cast<float4*>(sm + 9 * 4096);

    int ci = blockIdx.x;
    int tid = threadIdx.x;
    int g = tid & 63, rh = (tid >> 6) & 1, kh = tid >> 7;
    int slot = rh * 64 + g;
    int j0 = 4 * g;
    int rowoff = rh * 8 * DDIM;

    // load store-normed chunk rows [16,256]
    {
        const float4* src = reinterpret_cast<const float4*>(g_sn + (size_t)ci * CHK * DDIM);
        float4* dst = reinterpret_cast<float4*>(BX);
        for (int i = tid; i < CHK * DDIM / 4; i += 256) dst[i] = src[i];
    }
    __syncthreads();

    float4 acc[8];
#define GF_ZERO() do { _Pragma("unroll") for (int c = 0; c < 8; c++) acc[c] = f4zero(); } while (0)

    // keys = sn @ Wkv[:, :D]
    GF_ZERO();
    gf(BX + rowoff, Wkv + j0, 2 * DDIM, kh, acc);
    kreduce(acc, Bred, kh, slot);
    if (!kh) {
#pragma unroll
        for (int c = 0; c < 8; c++)
            *reinterpret_cast<float4*>(BK + rowoff + c * DDIM + j0) = acc[c];
    }
    __syncthreads();
    // vals = sn @ Wkv[:, D:]
    GF_ZERO();
    gf(BX + rowoff, Wkv + DDIM + j0, 2 * DDIM, kh, acc);
    kreduce(acc, Bred, kh, slot);
    if (!kh) {
#pragma unroll
        for (int c = 0; c < 8; c++)
            *reinterpret_cast<float4*>(BV + rowoff + c * DDIM + j0) = acc[c];
    }
    __syncthreads();

    // z0 = keys @ W0 ; a1 = silu(z0)
    GF_ZERO();
    gf(BK + rowoff, W0 + j0, DDIM, kh, acc);
    kreduce(acc, Bred, kh, slot);
    if (!kh) {
#pragma unroll
        for (int c = 0; c < 8; c++) {
            float4 z = acc[c];
            *reinterpret_cast<float4*>(Bz0 + rowoff + c * DDIM + j0) = z;
            float4 a = make_float4(z.x * sigm(z.x), z.y * sigm(z.y),
                                   z.z * sigm(z.z), z.w * sigm(z.w));
            *reinterpret_cast<float4*>(BA1 + rowoff + c * DDIM + j0) = a;
        }
    }
    __syncthreads();
    // z1, a2
    GF_ZERO();
    gf(BA1 + rowoff, W1 + j0, DDIM, kh, acc);
    kreduce(acc, Bred, kh, slot);
    if (!kh) {
#pragma unroll
        for (int c = 0; c < 8; c++) {
            float4 z = acc[c];
            *reinterpret_cast<float4*>(Bz1 + rowoff + c * DDIM + j0) = z;
            float4 a = make_float4(z.x * sigm(z.x), z.y * sigm(z.y),
                                   z.z * sigm(z.z), z.w * sigm(z.w));
            *reinterpret_cast<float4*>(BA2 + rowoff + c * DDIM + j0) = a;
        }
    }
    __syncthreads();
    // z2, a3
    GF_ZERO();
    gf(BA2 + rowoff, W2 + j0, DDIM, kh, acc);
    kreduce(acc, Bred, kh, slot);
    if (!kh) {
#pragma unroll
        for (int c = 0; c < 8; c++) {
            float4 z = acc[c];
            *reinterpret_cast<float4*>(Bz2 + rowoff + c * DDIM + j0) = z;
            float4 a = make_float4(z.x * sigm(z.x), z.y * sigm(z.y),
                                   z.z * sigm(z.z), z.w * sigm(z.w));
            *reinterpret_cast<float4*>(BA3 + rowoff + c * DDIM + j0) = a;
        }
    }
    __syncthreads();
    // pred = a3 @ W3 ; dz3 = (pred - vals)*2/D  (in place into BV)
    GF_ZERO();
    gf(BA3 + rowoff, W3 + j0, DDIM, kh, acc);
    kreduce(acc, Bred, kh, slot);
    if (!kh) {
#pragma unroll
        for (int c = 0; c < 8; c++) {
            float4* vp = reinterpret_cast<float4*>(BV + rowoff + c * DDIM + j0);
            float4 v = *vp;
            v.x = (acc[c].x - v.x) * (2.f / DDIM);
            v.y = (acc[c].y - v.y) * (2.f / DDIM);
            v.z = (acc[c].z - v.z) * (2.f / DDIM);
            v.w = (acc[c].w - v.w) * (2.f / DDIM);
            *vp = v;
        }
    }
    __syncthreads();

    float nlr = -g_scal[ci * 3 + 0];
    float* Sc = g_S + (size_t)ci * PPACK;

    // gW3
    gb(BA3, BV, Sc + 3 * WSZ, nlr, tid);
    // dz2 = (dz3 @ W3^T) * silu'(z2)  -> BX
    GF_ZERO();
    gf(BV + rowoff, g_WT + 2 * WSZ + j0, DDIM, kh, acc);
    kreduce(acc, Bred, kh, slot);
    if (!kh) {
#pragma unroll
        for (int c = 0; c < 8; c++) {
            float4 z = *reinterpret_cast<const float4*>(Bz2 + rowoff + c * DDIM + j0);
            float4 d = make_float4(acc[c].x * siluprime(z.x), acc[c].y * siluprime(z.y),
                                   acc[c].z * siluprime(z.z), acc[c].w * siluprime(z.w));
            *reinterpret_cast<float4*>(BX + rowoff + c * DDIM + j0) = d;
        }
    }
    __syncthreads();
    // gW2
    gb(BA2, BX, Sc + 2 * WSZ, nlr, tid);
    // dz1 = (dz2 @ W2^T) * silu'(z1) -> BV
    GF_ZERO();
    gf(BX + rowoff, g_WT + 1 * WSZ + j0, DDIM, kh, acc);
    kreduce(acc, Bred, kh, slot);
    if (!kh) {
#pragma unroll
        for (int c = 0; c < 8; c++) {
            float4 z = *reinterpret_cast<const float4*>(Bz1 + rowoff + c * DDIM + j0);
            float4 d = make_float4(acc[c].x * siluprime(z.x), acc[c].y * siluprime(z.y),
                                   acc[c].z * siluprime(z.z), acc[c].w * siluprime(z.w));
            *reinterpret_cast<float4*>(BV + rowoff + c * DDIM + j0) = d;
        }
    }
    __syncthreads();
    // gW1
    gb(BA1, BV, Sc + 1 * WSZ, nlr, tid);
    // dz0 = (dz1 @ W1^T) * silu'(z0) -> BX
    GF_ZERO();
    gf(BV + rowoff, g_WT + 0 * WSZ + j0, DDIM, kh, acc);
    kreduce(acc, Bred, kh, slot);
    if (!kh) {
#pragma unroll
        for (int c = 0; c < 8; c++) {
            float4 z = *reinterpret_cast<const float4*>(Bz0 + rowoff + c * DDIM + j0);
            float4 d = make_float4(acc[c].x * siluprime(z.x), acc[c].y * siluprime(z.y),
                                   acc[c].z * siluprime(z.z), acc[c].w * siluprime(z.w));
            *reinterpret_cast<float4*>(BX + rowoff + c * DDIM + j0) = d;
        }
    }
    __syncthreads();
    // gW0
    gb(BK, BX, Sc + 0 * WSZ, nlr, tid);
#undef GF_ZERO
}

// ------------------ K5: double gated scan over chunks (float4) ---------------
__global__ __launch_bounds__(256) void k_scan() {
    int b = blockIdx.y;
    __shared__ float sc[NCH * 2];
    if (threadIdx.x < NCH * 2) {
        int n = threadIdx.x >> 1;
        int w = threadIdx.x & 1;
        sc[threadIdx.x] = w ? (1.f - g_scal[(b * NCH + n) * 3 + 2])   // 1 - decay
                            : g_scal[(b * NCH + n) * 3 + 1];          // momentum gate
    }
    __syncthreads();
    size_t p4 = (size_t)blockIdx.x * 256 + threadIdx.x;
    const size_t stride4 = PPACK / 4;
    const float4* Sp = reinterpret_cast<const float4*>(g_S) + (size_t)b * NCH * stride4 + p4;
    float4* Up = reinterpret_cast<float4*>(g_U) + (size_t)b * NCH * stride4 + p4;
    float4 m = f4zero();
    float4 u = f4zero();
#pragma unroll 8
    for (int n = 0; n < NCH; n++) {
        float4 s = Sp[(size_t)n * stride4];
        float gm = sc[2 * n], gd = sc[2 * n + 1];
        m.x = fmaf(gm, m.x, s.x);
        m.y = fmaf(gm, m.y, s.y);
        m.z = fmaf(gm, m.z, s.z);
        m.w = fmaf(gm, m.w, s.w);
        u.x = fmaf(gd, u.x, m.x);
        u.y = fmaf(gd, u.y, m.y);
        u.z = fmaf(gd, u.z, m.z);
        u.w = fmaf(gd, u.w, m.w);
        Up[(size_t)n * stride4] = u;
    }
}

// ------------------ K6: retrieval MLP + postnorm + shift ---------------------
// Same 256-thread tiling as k_grad; weights are W+U with U streamed from HBM.
__global__ __launch_bounds__(256) void k_retrieve(const float* __restrict__ Wq,
                                                  const float* __restrict__ W0,
                                                  const float* __restrict__ W1,
                                                  const float* __restrict__ W2,
                                                  const float* __restrict__ W3,
                                                  const float* __restrict__ w_post,
                                                  float* __restrict__ out) {
    extern __shared__ float sm[];
    float* X = sm;                 // 4096
    float* Y = sm + 4096;          // 4096
    float4* Bred = reinterpret_cast<float4*>(sm + 8192);  // 4096 floats
    float* rr = sm + 12288;        // 16

    int ci = blockIdx.x;
    int tid = threadIdx.x;
    int g = tid & 63, rh = (tid >> 6) & 1, kh = tid >> 7;
    int slot = rh * 64 + g;
    int j0 = 4 * g;
    int rowoff = rh * 8 * DDIM;
    int b = ci >> 6, n = ci & (NCH - 1);

    {
        const float4* src = reinterpret_cast<const float4*>(g_rn + (size_t)ci * CHK * DDIM);
        float4* dst = reinterpret_cast<float4*>(X);
        for (int i = tid; i < CHK * DDIM / 4; i += 256) dst[i] = src[i];
    }
    __syncthreads();

    float4 acc[8];
    const float* U = g_U + (size_t)ci * PPACK;

#define GF_ZERO() do { _Pragma("unroll") for (int c = 0; c < 8; c++) acc[c] = f4zero(); } while (0)

    // q = rn @ Wq -> Y
    GF_ZERO();
    gf(X + rowoff, Wq + j0, DDIM, kh, acc);
    kreduce(acc, Bred, kh, slot);
    if (!kh) {
#pragma unroll
        for (int c = 0; c < 8; c++)
            *reinterpret_cast<float4*>(Y + rowoff + c * DDIM + j0) = acc[c];
    }
    __syncthreads();
    // layer 0: silu -> X
    GF_ZERO();
    gfwu(Y + rowoff, W0 + j0, U + 0 * WSZ + j0, kh, acc);
    kreduce(acc, Bred, kh, slot);
    if (!kh) {
#pragma unroll
        for (int c = 0; c < 8; c++) {
            float4 z = acc[c];
            *reinterpret_cast<float4*>(X + rowoff + c * DDIM + j0) =
                make_float4(z.x * sigm(z.x), z.y * sigm(z.y), z.z * sigm(z.z), z.w * sigm(z.w));
        }
    }
    __syncthreads();
    // layer 1: silu -> Y
    GF_ZERO();
    gfwu(X + rowoff, W1 + j0, U + 1 * WSZ + j0, kh, acc);
    kreduce(acc, Bred, kh, slot);
    if (!kh) {
#pragma unroll
        for (int c = 0; c < 8; c++) {
            float4 z = acc[c];
            *reinterpret_cast<float4*>(Y + rowoff + c * DDIM + j0) =
                make_float4(z.x * sigm(z.x), z.y * sigm(z.y), z.z * sigm(z.z), z.w * sigm(z.w));
        }
    }
    __syncthreads();
    // layer 2: silu -> X
    GF_ZERO();
    gfwu(Y + rowoff, W2 + j0, U + 2 * WSZ + j0, kh, acc);
    kreduce(acc, Bred, kh, slot);
    if (!kh) {
#pragma unroll
        for (int c = 0; c < 8; c++) {
            float4 z = acc[c];
            *reinterpret_cast<float4*>(X + rowoff + c * DDIM + j0) =
                make_float4(z.x * sigm(z.x), z.y * sigm(z.y), z.z * sigm(z.z), z.w * sigm(z.w));
        }
    }
    __syncthreads();
    // layer 3 (raw) -> Y
    GF_ZERO();
    gfwu(X + rowoff, W3 + j0, U + 3 * WSZ + j0, kh, acc);
    kreduce(acc, Bred, kh, slot);
    if (!kh) {
#pragma unroll
        for (int c = 0; c < 8; c++)
            *reinterpret_cast<float4*>(Y + rowoff + c * DDIM + j0) = acc[c];
    }
    __syncthreads();
#undef GF_ZERO

    // post rmsnorm per row (8 warps, 2 rows each)
    int warp = tid >> 5, lane = tid & 31;
    for (int c = warp; c < CHK; c += 8) {
        float s = 0.f;
        for (int i = lane; i < DDIM; i += 32) {
            float v = Y[c * DDIM + i];
            s = fmaf(v, v, s);
        }
        for (int o = 16; o; o >>= 1) s += __shfl_xor_sync(0xffffffffu, s, o);
        if (lane == 0) rr[c] = rsqrtf(s * (1.f / DDIM) + EPSR);
    }
    __syncthreads();

    // shift by C-1 and write (thread = one column)
    float wp = w_post[tid];
#pragma unroll
    for (int c = 0; c < CHK; c++) {
        int tdst = n * CHK + c + (CHK - 1);
        if (tdst < LSEQ)
            out[((size_t)b * LSEQ + tdst) * DDIM + tid] = Y[c * DDIM + tid] * rr[c] * wp;
    }
    if (n == 0) {
#pragma unroll
        for (int c = 0; c < CHK - 1; c++) out[((size_t)b * LSEQ + c) * DDIM + tid] = 0.f;
    }
}

// ----------------------------- launcher --------------------------------------
extern "C" void kernel_launch(void* const* d_in, const int* in_sizes, int n_in,
                              void* d_out, int out_size) {
    (void)in_sizes; (void)n_in; (void)out_size;
    const float* seq  = (const float*)d_in[0];
    const float* w_sn = (const float*)d_in[1];
    const float* w_rn = (const float*)d_in[2];
    const float* w_pn = (const float*)d_in[3];
    const float* Wq   = (const float*)d_in[4];
    const float* Wkv  = (const float*)d_in[5];
    const float* w_ad = (const float*)d_in[6];
    const float* w_mo = (const float*)d_in[7];
    const float* w_de = (const float*)d_in[8];
    const float* W0   = (const float*)d_in[9];
    const float* W1   = (const float*)d_in[10];
    const float* W2   = (const float*)d_in[11];
    const float* W3   = (const float*)d_in[12];
    float* out = (float*)d_out;

    const int grad_smem = 10 * 4096 * (int)sizeof(float);      // 160 KB
    const int retr_smem = (12288 + 32) * (int)sizeof(float);   // ~49.3 KB
    cudaFuncSetAttribute(k_grad, cudaFuncAttributeMaxDynamicSharedMemorySize, grad_smem);
    cudaFuncSetAttribute(k_retrieve, cudaFuncAttributeMaxDynamicSharedMemorySize, retr_smem);

    k_norms<<<BATCH * LSEQ, 256>>>(seq, w_sn, w_rn);
    k_gates<<<NCHUNKS, 256>>>(w_ad, w_mo, w_de);
    k_transpose<<<dim3(8, 8, 3), dim3(32, 8)>>>(W1, W2, W3);
    k_grad<<<NCHUNKS, 256, grad_smem>>>(Wkv, W0, W1, W2, W3);
    k_scan<<<dim3(PPACK / 1024, BATCH), 256>>>();
    k_retrieve<<<NCHUNKS, 256, retr_smem>>>(Wq, W0, W1, W2, W3, w_pn, out);
}

// round 17
// speedup vs baseline: 2.1394x; 1.4220x over previous
#include <cuda_runtime.h>
#include <math.h>

// ----------------------------- problem constants ----------------------------
#define DDIM 256
#define LSEQ 1024
#define BATCH 2
#define CHK 16
#define NCH 64                     // chunks per sequence
#define NCHUNKS (BATCH * NCH)      // 128 total chunks
#define PPACK (4 * DDIM * DDIM)    // 262144 packed grad elems per chunk
#define WSZ (DDIM * DDIM)          // 65536
#define EPSR 1.1920929e-07f

// ----------------------------- device scratch -------------------------------
__device__ float g_sn[BATCH * LSEQ * DDIM];     // store-norm rows
__device__ float g_rn[BATCH * LSEQ * DDIM];     // retrieve-norm rows, pre-shifted by C-1
__device__ float g_scal[NCHUNKS * 3];           // lr, mom, decay per chunk
__device__ float g_WT[3 * WSZ];                 // W1^T, W2^T, W3^T
__device__ float g_S[(size_t)NCHUNKS * PPACK];  // surprise = -lr * grads  (128 MB)
__device__ float g_U[(size_t)NCHUNKS * PPACK];  // cumulative updates      (128 MB)

// ----------------------------- helpers --------------------------------------
__device__ __forceinline__ float sigm(float z) { return 1.f / (1.f + __expf(-z)); }
__device__ __forceinline__ float siluprime(float z) {
    float s = sigm(z);
    return s * (1.f + z * (1.f - s));
}
__device__ __forceinline__ float4 f4zero() { return make_float4(0.f, 0.f, 0.f, 0.f); }

// Forward-type GEMM fragment: thread accumulates an [8 rows x 4 cols] tile over
// its 64-k quarter.  xs: smem [..,256] pre-offset to this thread's 8 rows.
// wg: global weight pre-offset to this thread's 4 columns.
__device__ __forceinline__ void gf(const float* __restrict__ xs,
                                   const float* __restrict__ wg, int ldw,
                                   int kh, float4 acc[8]) {
    const float* wp = wg + (size_t)(kh * 64) * ldw;
    const float* xp = xs + kh * 64;
#pragma unroll 2
    for (int kk = 0; kk < 64; kk += 4) {
        float4 w0 = *reinterpret_cast<const float4*>(wp);
        float4 w1 = *reinterpret_cast<const float4*>(wp + ldw);
        float4 w2 = *reinterpret_cast<const float4*>(wp + 2 * ldw);
        float4 w3 = *reinterpret_cast<const float4*>(wp + 3 * ldw);
        wp += 4 * ldw;
#pragma unroll
        for (int c = 0; c < 8; c++) {
            float4 xv = *reinterpret_cast<const float4*>(xp + c * DDIM + kk);
            acc[c].x = fmaf(xv.x, w0.x, acc[c].x);
            acc[c].x = fmaf(xv.y, w1.x, acc[c].x);
            acc[c].x = fmaf(xv.z, w2.x, acc[c].x);
            acc[c].x = fmaf(xv.w, w3.x, acc[c].x);
            acc[c].y = fmaf(xv.x, w0.y, acc[c].y);
            acc[c].y = fmaf(xv.y, w1.y, acc[c].y);
            acc[c].y = fmaf(xv.z, w2.y, acc[c].y);
            acc[c].y = fmaf(xv.w, w3.y, acc[c].y);
            acc[c].z = fmaf(xv.x, w0.z, acc[c].z);
            acc[c].z = fmaf(xv.y, w1.z, acc[c].z);
            acc[c].z = fmaf(xv.z, w2.z, acc[c].z);
            acc[c].z = fmaf(xv.w, w3.z, acc[c].z);
            acc[c].w = fmaf(xv.x, w0.w, acc[c].w);
            acc[c].w = fmaf(xv.y, w1.w, acc[c].w);
            acc[c].w = fmaf(xv.z, w2.w, acc[c].w);
            acc[c].w = fmaf(xv.w, w3.w, acc[c].w);
        }
    }
}

// Same but weight = W + U (fast weights), both global, same layout.
__device__ __forceinline__ void gfwu(const float* __restrict__ xs,
                                     const float* __restrict__ wg,
                                     const float* __restrict__ ug,
                                     int kh, float4 acc[8]) {
    const float* wp = wg + (size_t)(kh * 64) * DDIM;
    const float* up = ug + (size_t)(kh * 64) * DDIM;
    const float* xp = xs + kh * 64;
#pragma unroll 2
    for (int kk = 0; kk < 64; kk += 4) {
        float4 w0 = *reinterpret_cast<const float4*>(wp);
        float4 w1 = *reinterpret_cast<const float4*>(wp + DDIM);
        float4 w2 = *reinterpret_cast<const float4*>(wp + 2 * DDIM);
        float4 w3 = *reinterpret_cast<const float4*>(wp + 3 * DDIM);
        float4 u0 = *reinterpret_cast<const float4*>(up);
        float4 u1 = *reinterpret_cast<const float4*>(up + DDIM);
        float4 u2 = *reinterpret_cast<const float4*>(up + 2 * DDIM);
        float4 u3 = *reinterpret_cast<const float4*>(up + 3 * DDIM);
        wp += 4 * DDIM;
        up += 4 * DDIM;
        w0.x += u0.x; w0.y += u0.y; w0.z += u0.z; w0.w += u0.w;
        w1.x += u1.x; w1.y += u1.y; w1.z += u1.z; w1.w += u1.w;
        w2.x += u2.x; w2.y += u2.y; w2.z += u2.z; w2.w += u2.w;
        w3.x += u3.x; w3.y += u3.y; w3.z += u3.z; w3.w += u3.w;
#pragma unroll
        for (int c = 0; c < 8; c++) {
            float4 xv = *reinterpret_cast<const float4*>(xp + c * DDIM + kk);
            acc[c].x = fmaf(xv.x, w0.x, acc[c].x);
            acc[c].x = fmaf(xv.y, w1.x, acc[c].x);
            acc[c].x = fmaf(xv.z, w2.x, acc[c].x);
            acc[c].x = fmaf(xv.w, w3.x, acc[c].x);
            acc[c].y = fmaf(xv.x, w0.y, acc[c].y);
            acc[c].y = fmaf(xv.y, w1.y, acc[c].y);
            acc[c].y = fmaf(xv.z, w2.y, acc[c].y);
            acc[c].y = fmaf(xv.w, w3.y, acc[c].y);
            acc[c].z = fmaf(xv.x, w0.z, acc[c].z);
            acc[c].z = fmaf(xv.y, w1.z, acc[c].z);
            acc[c].z = fmaf(xv.z, w2.z, acc[c].z);
            acc[c].z = fmaf(xv.w, w3.z, acc[c].z);
            acc[c].w = fmaf(xv.x, w0.w, acc[c].w);
            acc[c].w = fmaf(xv.y, w1.w, acc[c].w);
            acc[c].w = fmaf(xv.z, w2.w, acc[c].w);
            acc[c].w = fmaf(xv.w, w3.w, acc[c].w);
        }
    }
}

// 4-way k-split reduction: kh 1..3 deposit partials; kh==0 adds all three.
// Bred = float4[3][8][128]; slot = rh*64+g (conflict-free).
__device__ __forceinline__ void kreduce4(float4 acc[8], float4* Bred, int kh, int slot) {
    if (kh) {
        float4* dst = Bred + (kh - 1) * 1024;
#pragma unroll
        for (int c = 0; c < 8; c++) dst[c * 128 + slot] = acc[c];
    }
    __syncthreads();
    if (!kh) {
#pragma unroll
        for (int c = 0; c < 8; c++) {
            float4 t0 = Bred[0 * 1024 + c * 128 + slot];
            float4 t1 = Bred[1 * 1024 + c * 128 + slot];
            float4 t2 = Bred[2 * 1024 + c * 128 + slot];
            acc[c].x += t0.x + t1.x + t2.x;
            acc[c].y += t0.y + t1.y + t2.y;
            acc[c].z += t0.z + t1.z + t2.z;
            acc[c].w += t0.w + t1.w + t2.w;
        }
    }
}

// Weight-grad: Sout[p][q] = nlr * sum_c A[c][p] * D[c][q].
// 512 threads: g = tid&63 (4 q-cols), pq = tid>>6 (32 p-rows each).
__device__ __forceinline__ void gb(const float* __restrict__ A,
                                   const float* __restrict__ D,
                                   float* __restrict__ Sout, float nlr, int tid) {
    int g = tid & 63, pq = tid >> 6;
    int q0 = 4 * g;
    float4 dj[CHK];
#pragma unroll
    for (int c = 0; c < CHK; c++) {
        float4 d = *reinterpret_cast<const float4*>(D + c * DDIM + q0);
        dj[c].x = d.x * nlr; dj[c].y = d.y * nlr;
        dj[c].z = d.z * nlr; dj[c].w = d.w * nlr;
    }
    int pend = pq * 32 + 32;
    for (int p0 = pq * 32; p0 < pend; p0 += 4) {
        float4 r0 = f4zero(), r1 = f4zero(), r2 = f4zero(), r3 = f4zero();
#pragma unroll
        for (int c = 0; c < CHK; c++) {
            float4 a = *reinterpret_cast<const float4*>(A + c * DDIM + p0);  // broadcast
            r0.x = fmaf(a.x, dj[c].x, r0.x); r0.y = fmaf(a.x, dj[c].y, r0.y);
            r0.z = fmaf(a.x, dj[c].z, r0.z); r0.w = fmaf(a.x, dj[c].w, r0.w);
            r1.x = fmaf(a.y, dj[c].x, r1.x); r1.y = fmaf(a.y, dj[c].y, r1.y);
            r1.z = fmaf(a.y, dj[c].z, r1.z); r1.w = fmaf(a.y, dj[c].w, r1.w);
            r2.x = fmaf(a.z, dj[c].x, r2.x); r2.y = fmaf(a.z, dj[c].y, r2.y);
            r2.z = fmaf(a.z, dj[c].z, r2.z); r2.w = fmaf(a.z, dj[c].w, r2.w);
            r3.x = fmaf(a.w, dj[c].x, r3.x); r3.y = fmaf(a.w, dj[c].y, r3.y);
            r3.z = fmaf(a.w, dj[c].z, r3.z); r3.w = fmaf(a.w, dj[c].w, r3.w);
        }
        *reinterpret_cast<float4*>(Sout + (size_t)(p0 + 0) * DDIM + q0) = r0;
        *reinterpret_cast<float4*>(Sout + (size_t)(p0 + 1) * DDIM + q0) = r1;
        *reinterpret_cast<float4*>(Sout + (size_t)(p0 + 2) * DDIM + q0) = r2;
        *reinterpret_cast<float4*>(Sout + (size_t)(p0 + 3) * DDIM + q0) = r3;
    }
}

// ------------------ K1: rmsnorms (store + shifted retrieve) -----------------
__global__ __launch_bounds__(256) void k_norms(const float* __restrict__ seq,
                                               const float* __restrict__ w_store,
                                               const float* __restrict__ w_ret) {
    int gt = blockIdx.x;  // global token 0..2047
    int d = threadIdx.x;
    float x = seq[gt * DDIM + d];
    __shared__ float red[256];
    red[d] = x * x;
    __syncthreads();
    for (int s = 128; s > 0; s >>= 1) {
        if (d < s) red[d] += red[d + s];
        __syncthreads();
    }
    float r = rsqrtf(red[0] * (1.f / DDIM) + EPSR);
    g_sn[gt * DDIM + d] = x * r * w_store[d];
    float rv = x * r * w_ret[d];
    int b = gt >> 10, t = gt & (LSEQ - 1);
    if (t >= CHK - 1)
        g_rn[(b * LSEQ + t - (CHK - 1)) * DDIM + d] = rv;
    else
        g_rn[(b * LSEQ + (LSEQ - (CHK - 1)) + t) * DDIM + d] = 0.f;
}

// ------------------ K2: per-chunk gate scalars -------------------------------
__global__ __launch_bounds__(256) void k_gates(const float* __restrict__ wa,
                                               const float* __restrict__ wm,
                                               const float* __restrict__ wd) {
    int ci = blockIdx.x;
    int d = threadIdx.x;
    const float* base = g_sn + ci * (CHK * DDIM) + d;
    float s = 0.f;
#pragma unroll
    for (int c = 0; c < CHK; c++) s += base[c * DDIM];
    float m = s * (1.f / CHK);
    float v[3] = {m * wa[d], m * wm[d], m * wd[d]};
    __shared__ float red[256];
    for (int i = 0; i < 3; i++) {
        red[d] = v[i];
        __syncthreads();
        for (int s2 = 128; s2 > 0; s2 >>= 1) {
            if (d < s2) red[d] += red[d + s2];
            __syncthreads();
        }
        if (d == 0) g_scal[ci * 3 + i] = 1.f / (1.f + __expf(-red[0]));
        __syncthreads();
    }
}

// ------------------ K3: transpose W1..W3 for backward ------------------------
__global__ __launch_bounds__(256) void k_transpose(const float* __restrict__ W1,
                                                   const float* __restrict__ W2,
                                                   const float* __restrict__ W3) {
    __shared__ float tile[32][33];
    int m = blockIdx.z;
    const float* W = (m == 0) ? W1 : (m == 1) ? W2 : W3;
    int bx = blockIdx.x * 32, by = blockIdx.y * 32;
    int x = threadIdx.x, y = threadIdx.y;  // 32 x 8
    for (int i = 0; i < 32; i += 8) tile[y + i][x] = W[(by + y + i) * DDIM + bx + x];
    __syncthreads();
    for (int i = 0; i < 32; i += 8)
        g_WT[m * WSZ + (bx + y + i) * DDIM + by + x] = tile[x][y + i];
}

// ------------------ K4: per-chunk fwd + bwd grads → S ------------------------
// 512 threads: g = tid&63 (cols 4g..4g+3), rh = (tid>>6)&1 (rows rh*8..),
// kh = tid>>7 (k quarter 0..3).  Warps uniform in (rh,kh) -> broadcast x loads.
__global__ __launch_bounds__(512) void k_grad(const float* __restrict__ Wkv,
                                              const float* __restrict__ W0,
                                              const float* __restrict__ W1,
                                              const float* __restrict__ W2,
                                              const float* __restrict__ W3) {
    extern __shared__ float sm[];
    float* BX  = sm + 0 * 4096;  // sn -> dz2 -> dz0
    float* BK  = sm + 1 * 4096;  // keys (a0)
    float* BV  = sm + 2 * 4096;  // vals -> dz3 -> dz1
    float* BA1 = sm + 3 * 4096;
    float* BA2 = sm + 4 * 4096;
    float* BA3 = sm + 5 * 4096;
    float* Bz0 = sm + 6 * 4096;
    float* Bz1 = sm + 7 * 4096;
    float* Bz2 = sm + 8 * 4096;
    float4* Bred = reinterpret_cast<float4*>(sm + 9 * 4096);  // 3 * 16KB

    int ci = blockIdx.x;
    int tid = threadIdx.x;
    int g = tid & 63, rh = (tid >> 6) & 1, kh = tid >> 7;
    int slot = rh * 64 + g;
    int j0 = 4 * g;
    int rowoff = rh * 8 * DDIM;

    // load store-normed chunk rows [16,256]
    {
        const float4* src = reinterpret_cast<const float4*>(g_sn + (size_t)ci * CHK * DDIM);
        float4* dst = reinterpret_cast<float4*>(BX);
        for (int i = tid; i < CHK * DDIM / 4; i += 512) dst[i] = src[i];
    }
    __syncthreads();

    float4 acc[8];
#define GF_ZERO() do { _Pragma("unroll") for (int c = 0; c < 8; c++) acc[c] = f4zero(); } while (0)

    // keys = sn @ Wkv[:, :D]
    GF_ZERO();
    gf(BX + rowoff, Wkv + j0, 2 * DDIM, kh, acc);
    kreduce4(acc, Bred, kh, slot);
    if (!kh) {
#pragma unroll
        for (int c = 0; c < 8; c++)
            *reinterpret_cast<float4*>(BK + rowoff + c * DDIM + j0) = acc[c];
    }
    __syncthreads();
    // vals = sn @ Wkv[:, D:]
    GF_ZERO();
    gf(BX + rowoff, Wkv + DDIM + j0, 2 * DDIM, kh, acc);
    kreduce4(acc, Bred, kh, slot);
    if (!kh) {
#pragma unroll
        for (int c = 0; c < 8; c++)
            *reinterpret_cast<float4*>(BV + rowoff + c * DDIM + j0) = acc[c];
    }
    __syncthreads();

    // z0 = keys @ W0 ; a1 = silu(z0)
    GF_ZERO();
    gf(BK + rowoff, W0 + j0, DDIM, kh, acc);
    kreduce4(acc, Bred, kh, slot);
    if (!kh) {
#pragma unroll
        for (int c = 0; c < 8; c++) {
            float4 z = acc[c];
            *reinterpret_cast<float4*>(Bz0 + rowoff + c * DDIM + j0) = z;
            float4 a = make_float4(z.x * sigm(z.x), z.y * sigm(z.y),
                                   z.z * sigm(z.z), z.w * sigm(z.w));
            *reinterpret_cast<float4*>(BA1 + rowoff + c * DDIM + j0) = a;
        }
    }
    __syncthreads();
    // z1, a2
    GF_ZERO();
    gf(BA1 + rowoff, W1 + j0, DDIM, kh, acc);
    kreduce4(acc, Bred, kh, slot);
    if (!kh) {
#pragma unroll
        for (int c = 0; c < 8; c++) {
            float4 z = acc[c];
            *reinterpret_cast<float4*>(Bz1 + rowoff + c * DDIM + j0) = z;
            float4 a = make_float4(z.x * sigm(z.x), z.y * sigm(z.y),
                                   z.z * sigm(z.z), z.w * sigm(z.w));
            *reinterpret_cast<float4*>(BA2 + rowoff + c * DDIM + j0) = a;
        }
    }
    __syncthreads();
    // z2, a3
    GF_ZERO();
    gf(BA2 + rowoff, W2 + j0, DDIM, kh, acc);
    kreduce4(acc, Bred, kh, slot);
    if (!kh) {
#pragma unroll
        for (int c = 0; c < 8; c++) {
            float4 z = acc[c];
            *reinterpret_cast<float4*>(Bz2 + rowoff + c * DDIM + j0) = z;
            float4 a = make_float4(z.x * sigm(z.x), z.y * sigm(z.y),
                                   z.z * sigm(z.z), z.w * sigm(z.w));
            *reinterpret_cast<float4*>(BA3 + rowoff + c * DDIM + j0) = a;
        }
    }
    __syncthreads();
    // pred = a3 @ W3 ; dz3 = (pred - vals)*2/D  (in place into BV)
    GF_ZERO();
    gf(BA3 + rowoff, W3 + j0, DDIM, kh, acc);
    kreduce4(acc, Bred, kh, slot);
    if (!kh) {
#pragma unroll
        for (int c = 0; c < 8; c++) {
            float4* vp = reinterpret_cast<float4*>(BV + rowoff + c * DDIM + j0);
            float4 v = *vp;
            v.x = (acc[c].x - v.x) * (2.f / DDIM);
            v.y = (acc[c].y - v.y) * (2.f / DDIM);
            v.z = (acc[c].z - v.z) * (2.f / DDIM);
            v.w = (acc[c].w - v.w) * (2.f / DDIM);
            *vp = v;
        }
    }
    __syncthreads();

    float nlr = -g_scal[ci * 3 + 0];
    float* Sc = g_S + (size_t)ci * PPACK;

    // gW3
    gb(BA3, BV, Sc + 3 * WSZ, nlr, tid);
    // dz2 = (dz3 @ W3^T) * silu'(z2)  -> BX
    GF_ZERO();
    gf(BV + rowoff, g_WT + 2 * WSZ + j0, DDIM, kh, acc);
    kreduce4(acc, Bred, kh, slot);
    if (!kh) {
#pragma unroll
        for (int c = 0; c < 8; c++) {
            float4 z = *reinterpret_cast<const float4*>(Bz2 + rowoff + c * DDIM + j0);
            float4 d = make_float4(acc[c].x * siluprime(z.x), acc[c].y * siluprime(z.y),
                                   acc[c].z * siluprime(z.z), acc[c].w * siluprime(z.w));
            *reinterpret_cast<float4*>(BX + rowoff + c * DDIM + j0) = d;
        }
    }
    __syncthreads();
    // gW2
    gb(BA2, BX, Sc + 2 * WSZ, nlr, tid);
    // dz1 = (dz2 @ W2^T) * silu'(z1) -> BV
    GF_ZERO();
    gf(BX + rowoff, g_WT + 1 * WSZ + j0, DDIM, kh, acc);
    kreduce4(acc, Bred, kh, slot);
    if (!kh) {
#pragma unroll
        for (int c = 0; c < 8; c++) {
            float4 z = *reinterpret_cast<const float4*>(Bz1 + rowoff + c * DDIM + j0);
            float4 d = make_float4(acc[c].x * siluprime(z.x), acc[c].y * siluprime(z.y),
                                   acc[c].z * siluprime(z.z), acc[c].w * siluprime(z.w));
            *reinterpret_cast<float4*>(BV + rowoff + c * DDIM + j0) = d;
        }
    }
    __syncthreads();
    // gW1
    gb(BA1, BV, Sc + 1 * WSZ, nlr, tid);
    // dz0 = (dz1 @ W1^T) * silu'(z0) -> BX
    GF_ZERO();
    gf(BV + rowoff, g_WT + 0 * WSZ + j0, DDIM, kh, acc);
    kreduce4(acc, Bred, kh, slot);
    if (!kh) {
#pragma unroll
        for (int c = 0; c < 8; c++) {
            float4 z = *reinterpret_cast<const float4*>(Bz0 + rowoff + c * DDIM + j0);
            float4 d = make_float4(acc[c].x * siluprime(z.x), acc[c].y * siluprime(z.y),
                                   acc[c].z * siluprime(z.z), acc[c].w * siluprime(z.w));
            *reinterpret_cast<float4*>(BX + rowoff + c * DDIM + j0) = d;
        }
    }
    __syncthreads();
    // gW0
    gb(BK, BX, Sc + 0 * WSZ, nlr, tid);
#undef GF_ZERO
}

// ------------------ K5: double gated scan over chunks (float4) ---------------
__global__ __launch_bounds__(256) void k_scan() {
    int b = blockIdx.y;
    __shared__ float sc[NCH * 2];
    if (threadIdx.x < NCH * 2) {
        int n = threadIdx.x >> 1;
        int w = threadIdx.x & 1;
        sc[threadIdx.x] = w ? (1.f - g_scal[(b * NCH + n) * 3 + 2])   // 1 - decay
                            : g_scal[(b * NCH + n) * 3 + 1];          // momentum gate
    }
    __syncthreads();
    size_t p4 = (size_t)blockIdx.x * 256 + threadIdx.x;
    const size_t stride4 = PPACK / 4;
    const float4* Sp = reinterpret_cast<const float4*>(g_S) + (size_t)b * NCH * stride4 + p4;
    float4* Up = reinterpret_cast<float4*>(g_U) + (size_t)b * NCH * stride4 + p4;
    float4 m = f4zero();
    float4 u = f4zero();
#pragma unroll 8
    for (int n = 0; n < NCH; n++) {
        float4 s = Sp[(size_t)n * stride4];
        float gm = sc[2 * n], gd = sc[2 * n + 1];
        m.x = fmaf(gm, m.x, s.x);
        m.y = fmaf(gm, m.y, s.y);
        m.z = fmaf(gm, m.z, s.z);
        m.w = fmaf(gm, m.w, s.w);
        u.x = fmaf(gd, u.x, m.x);
        u.y = fmaf(gd, u.y, m.y);
        u.z = fmaf(gd, u.z, m.z);
        u.w = fmaf(gd, u.w, m.w);
        Up[(size_t)n * stride4] = u;
    }
}

// ------------------ K6: retrieval MLP + postnorm + shift ---------------------
// Same 512-thread tiling as k_grad; weights are W+U with U streamed from HBM.
__global__ __launch_bounds__(512) void k_retrieve(const float* __restrict__ Wq,
                                                  const float* __restrict__ W0,
                                                  const float* __restrict__ W1,
                                                  const float* __restrict__ W2,
                                                  const float* __restrict__ W3,
                                                  const float* __restrict__ w_post,
                                                  float* __restrict__ out) {
    extern __shared__ float sm[];
    float* X = sm;                                          // 4096
    float* Y = sm + 4096;                                   // 4096
    float4* Bred = reinterpret_cast<float4*>(sm + 8192);    // 3 * 4096 floats
    float* rr = sm + 8192 + 12288;                          // 16

    int ci = blockIdx.x;
    int tid = threadIdx.x;
    int g = tid & 63, rh = (tid >> 6) & 1, kh = tid >> 7;
    int slot = rh * 64 + g;
    int j0 = 4 * g;
    int rowoff = rh * 8 * DDIM;
    int b = ci >> 6, n = ci & (NCH - 1);

    {
        const float4* src = reinterpret_cast<const float4*>(g_rn + (size_t)ci * CHK * DDIM);
        float4* dst = reinterpret_cast<float4*>(X);
        for (int i = tid; i < CHK * DDIM / 4; i += 512) dst[i] = src[i];
    }
    __syncthreads();

    float4 acc[8];
    const float* U = g_U + (size_t)ci * PPACK;

#define GF_ZERO() do { _Pragma("unroll") for (int c = 0; c < 8; c++) acc[c] = f4zero(); } while (0)

    // q = rn @ Wq -> Y
    GF_ZERO();
    gf(X + rowoff, Wq + j0, DDIM, kh, acc);
    kreduce4(acc, Bred, kh, slot);
    if (!kh) {
#pragma unroll
        for (int c = 0; c < 8; c++)
            *reinterpret_cast<float4*>(Y + rowoff + c * DDIM + j0) = acc[c];
    }
    __syncthreads();
    // layer 0: silu -> X
    GF_ZERO();
    gfwu(Y + rowoff, W0 + j0, U + 0 * WSZ + j0, kh, acc);
    kreduce4(acc, Bred, kh, slot);
    if (!kh) {
#pragma unroll
        for (int c = 0; c < 8; c++) {
            float4 z = acc[c];
            *reinterpret_cast<float4*>(X + rowoff + c * DDIM + j0) =
                make_float4(z.x * sigm(z.x), z.y * sigm(z.y), z.z * sigm(z.z), z.w * sigm(z.w));
        }
    }
    __syncthreads();
    // layer 1: silu -> Y
    GF_ZERO();
    gfwu(X + rowoff, W1 + j0, U + 1 * WSZ + j0, kh, acc);
    kreduce4(acc, Bred, kh, slot);
    if (!kh) {
#pragma unroll
        for (int c = 0; c < 8; c++) {
            float4 z = acc[c];
            *reinterpret_cast<float4*>(Y + rowoff + c * DDIM + j0) =
                make_float4(z.x * sigm(z.x), z.y * sigm(z.y), z.z * sigm(z.z), z.w * sigm(z.w));
        }
    }
    __syncthreads();
    // layer 2: silu -> X
    GF_ZERO();
    gfwu(Y + rowoff, W2 + j0, U + 2 * WSZ + j0, kh, acc);
    kreduce4(acc, Bred, kh, slot);
    if (!kh) {
#pragma unroll
        for (int c = 0; c < 8; c++) {
            float4 z = acc[c];
            *reinterpret_cast<float4*>(X + rowoff + c * DDIM + j0) =
                make_float4(z.x * sigm(z.x), z.y * sigm(z.y), z.z * sigm(z.z), z.w * sigm(z.w));
        }
    }
    __syncthreads();
    // layer 3 (raw) -> Y
    GF_ZERO();
    gfwu(X + rowoff, W3 + j0, U + 3 * WSZ + j0, kh, acc);
    kreduce4(acc, Bred, kh, slot);
    if (!kh) {
#pragma unroll
        for (int c = 0; c < 8; c++)
            *reinterpret_cast<float4*>(Y + rowoff + c * DDIM + j0) = acc[c];
    }
    __syncthreads();
#undef GF_ZERO

    // post rmsnorm per row (16 warps, one row each)
    int warp = tid >> 5, lane = tid & 31;
    if (warp < CHK) {
        int c = warp;
        float s = 0.f;
        for (int i = lane; i < DDIM; i += 32) {
            float v = Y[c * DDIM + i];
            s = fmaf(v, v, s);
        }
        for (int o = 16; o; o >>= 1) s += __shfl_xor_sync(0xffffffffu, s, o);
        if (lane == 0) rr[c] = rsqrtf(s * (1.f / DDIM) + EPSR);
    }
    __syncthreads();

    // shift by C-1 and write: col = tid&255, half = tid>>8 -> 8 rows each
    int col = tid & 255, half = tid >> 8;
    float wp = w_post[col];
#pragma unroll
    for (int cc = 0; cc < 8; cc++) {
        int c = half * 8 + cc;
        int tdst = n * CHK + c + (CHK - 1);
        if (tdst < LSEQ)
            out[((size_t)b * LSEQ + tdst) * DDIM + col] = Y[c * DDIM + col] * rr[c] * wp;
    }
    if (n == 0) {
        for (int c = half * 8; c < half * 8 + 8 && c < CHK - 1; c++)
            out[((size_t)b * LSEQ + c) * DDIM + col] = 0.f;
    }
}

// ----------------------------- launcher --------------------------------------
extern "C" void kernel_launch(void* const* d_in, const int* in_sizes, int n_in,
                              void* d_out, int out_size) {
    (void)in_sizes; (void)n_in; (void)out_size;
    const float* seq  = (const float*)d_in[0];
    const float* w_sn = (const float*)d_in[1];
    const float* w_rn = (const float*)d_in[2];
    const float* w_pn = (const float*)d_in[3];
    const float* Wq   = (const float*)d_in[4];
    const float* Wkv  = (const float*)d_in[5];
    const float* w_ad = (const float*)d_in[6];
    const float* w_mo = (const float*)d_in[7];
    const float* w_de = (const float*)d_in[8];
    const float* W0   = (const float*)d_in[9];
    const float* W1   = (const float*)d_in[10];
    const float* W2   = (const float*)d_in[11];
    const float* W3   = (const float*)d_in[12];
    float* out = (float*)d_out;

    const int grad_smem = (9 * 4096 + 12288) * (int)sizeof(float);   // 192 KB
    const int retr_smem = (8192 + 12288 + 32) * (int)sizeof(float);  // ~82 KB
    cudaFuncSetAttribute(k_grad, cudaFuncAttributeMaxDynamicSharedMemorySize, grad_smem);
    cudaFuncSetAttribute(k_retrieve, cudaFuncAttributeMaxDynamicSharedMemorySize, retr_smem);

    k_norms<<<BATCH * LSEQ, 256>>>(seq, w_sn, w_rn);
    k_gates<<<NCHUNKS, 256>>>(w_ad, w_mo, w_de);
    k_transpose<<<dim3(8, 8, 3), dim3(32, 8)>>>(W1, W2, W3);
    k_grad<<<NCHUNKS, 512, grad_smem>>>(Wkv, W0, W1, W2, W3);
    k_scan<<<dim3(PPACK / 1024, BATCH), 256>>>();
    k_retrieve<<<NCHUNKS, 512, retr_smem>>>(Wq, W0, W1, W2, W3, w_pn, out);
}